// round 1
// baseline (speedup 1.0000x reference)
#include <cuda_runtime.h>
#include <math.h>

#define B_ 32
#define N_ 1024
#define C_ 64
#define BN (B_ * N_)

// scratch (allocation-free rule: use __device__ globals)
__device__ float g_h[BN * C_];
__device__ float g_ssrc[BN];
__device__ float g_sdst[BN];

// ---------------------------------------------------------------------------
// Kernel A: h = input @ W   (32768 x 64 rows, K=64)
// 64 rows per block, 256 threads, W + input tile staged in smem.
// ---------------------------------------------------------------------------
__global__ void __launch_bounds__(256) gemm_h_kernel(const float* __restrict__ in,
                                                     const float* __restrict__ W) {
    __shared__ float Ws[64 * 64];
    __shared__ float Is[64 * 64];
    const int t = threadIdx.x;
    const int row0 = blockIdx.x * 64;

    // load W (4096 floats) and input tile (4096 floats), coalesced float4
    const float4* W4 = (const float4*)W;
    float4* Ws4 = (float4*)Ws;
#pragma unroll
    for (int q = 0; q < 4; q++) Ws4[t + q * 256] = W4[t + q * 256];
    const float4* in4 = (const float4*)(in + row0 * 64);
    float4* Is4 = (float4*)Is;
#pragma unroll
    for (int q = 0; q < 4; q++) Is4[t + q * 256] = in4[t + q * 256];
    __syncthreads();

    const int c = t & 63;
    const int r0 = t >> 6;  // 0..3
    float acc[16];
#pragma unroll
    for (int q = 0; q < 16; q++) acc[q] = 0.0f;

#pragma unroll
    for (int k = 0; k < 64; k++) {
        float w = Ws[k * 64 + c];
#pragma unroll
        for (int q = 0; q < 16; q++)
            acc[q] = fmaf(Is[(r0 + 4 * q) * 64 + k], w, acc[q]);
    }
#pragma unroll
    for (int q = 0; q < 16; q++)
        g_h[(row0 + r0 + 4 * q) * 64 + c] = acc[q];
}

// ---------------------------------------------------------------------------
// Kernel B: s_src[row] = h[row]·a[0:64],  s_dst[row] = h[row]·a[64:128]
// one warp per row
// ---------------------------------------------------------------------------
__global__ void __launch_bounds__(256) dots_kernel(const float* __restrict__ a) {
    const int row = blockIdx.x * 8 + (threadIdx.x >> 5);
    const int lane = threadIdx.x & 31;
    const float* hr = g_h + row * 64;
    float h0 = hr[lane], h1 = hr[lane + 32];
    float ss = h0 * a[lane] + h1 * a[lane + 32];
    float sd = h0 * a[64 + lane] + h1 * a[96 + lane];
#pragma unroll
    for (int o = 16; o; o >>= 1) {
        ss += __shfl_xor_sync(0xffffffffu, ss, o);
        sd += __shfl_xor_sync(0xffffffffu, sd, o);
    }
    if (lane == 0) {
        g_ssrc[row] = ss;
        g_sdst[row] = sd;
    }
}

// ---------------------------------------------------------------------------
// Kernel C: fused masked attention + PV + ELU (flash-attention style).
// Block = (batch b, i-tile of 64 rows). 256 threads = 8 warps, warp owns
// 8 i-rows; lane owns columns {lane, lane+32}. Loop over 16 j-tiles of 64.
// ---------------------------------------------------------------------------
__global__ void __launch_bounds__(256, 3) attn_kernel(const float* __restrict__ adj,
                                                      float* __restrict__ out) {
    __shared__ float hs[64 * 64];      // h tile  [j][c]
    __shared__ float ps[8][8 * 64];    // per-warp p scratch [r][j]
    __shared__ float sdst_s[64];

    const int b = blockIdx.y;
    const int i0 = blockIdx.x * 64;
    const int t = threadIdx.x;
    const int w = t >> 5;
    const int lane = t & 31;

    float m[8], l[8], acc0[8], acc1[8], ssr[8];
#pragma unroll
    for (int r = 0; r < 8; r++) {
        m[r] = -INFINITY;
        l[r] = 0.0f;
        acc0[r] = 0.0f;
        acc1[r] = 0.0f;
        ssr[r] = g_ssrc[b * N_ + i0 + w * 8 + r];
    }
    const float* hb = g_h + b * N_ * C_;

    for (int jt = 0; jt < 16; jt++) {
        const int j0 = jt * 64;
        __syncthreads();  // protect hs from previous iteration's readers
        // stage h tile (4096 floats) coalesced
        const float4* hsrc = (const float4*)(hb + j0 * 64);
        float4* hd = (float4*)hs;
#pragma unroll
        for (int q = 0; q < 4; q++) hd[t + q * 256] = hsrc[t + q * 256];
        if (t < 64) sdst_s[t] = g_sdst[b * N_ + j0 + t];

        // prefetch adj values for this warp's 8 rows (L2-resident, MLP=16)
        float av0[8], av1[8];
#pragma unroll
        for (int r = 0; r < 8; r++) {
            const float* ap = adj + (i0 + w * 8 + r) * N_ + j0;
            av0[r] = __ldg(ap + lane);
            av1[r] = __ldg(ap + lane + 32);
        }
        __syncthreads();

        // scores + online softmax update
#pragma unroll
        for (int r = 0; r < 8; r++) {
            float sd0 = sdst_s[lane], sd1 = sdst_s[lane + 32];
            float x0 = ssr[r] + sd0;
            x0 = x0 >= 0.0f ? x0 : 0.2f * x0;
            float x1 = ssr[r] + sd1;
            x1 = x1 >= 0.0f ? x1 : 0.2f * x1;
            x0 = av0[r] > 0.5f ? x0 : -9e15f;
            x1 = av1[r] > 0.5f ? x1 : -9e15f;
            float tm = fmaxf(x0, x1);
#pragma unroll
            for (int o = 16; o; o >>= 1)
                tm = fmaxf(tm, __shfl_xor_sync(0xffffffffu, tm, o));
            float mn = fmaxf(m[r], tm);
            float sc = __expf(m[r] - mn);
            float p0 = __expf(x0 - mn);
            float p1 = __expf(x1 - mn);
            float sum = p0 + p1;
#pragma unroll
            for (int o = 16; o; o >>= 1)
                sum += __shfl_xor_sync(0xffffffffu, sum, o);
            l[r] = l[r] * sc + sum;
            acc0[r] *= sc;
            acc1[r] *= sc;
            m[r] = mn;
            ps[w][r * 64 + lane] = p0;
            ps[w][r * 64 + lane + 32] = p1;
        }
        __syncwarp();

        // PV accumulate: hoist h loads across the 8 r's (10 LDS : 16 FFMA)
#pragma unroll 4
        for (int jj = 0; jj < 64; jj++) {
            float hv0 = hs[jj * 64 + lane];
            float hv1 = hs[jj * 64 + lane + 32];
#pragma unroll
            for (int r = 0; r < 8; r++) {
                float p = ps[w][r * 64 + jj];
                acc0[r] = fmaf(p, hv0, acc0[r]);
                acc1[r] = fmaf(p, hv1, acc1[r]);
            }
        }
    }

    // epilogue: normalize + ELU, coalesced store
#pragma unroll
    for (int r = 0; r < 8; r++) {
        const int i = i0 + w * 8 + r;
        float inv = 1.0f / l[r];
        float v0 = acc0[r] * inv;
        float v1 = acc1[r] * inv;
        v0 = v0 > 0.0f ? v0 : (__expf(v0) - 1.0f);
        v1 = v1 > 0.0f ? v1 : (__expf(v1) - 1.0f);
        float* op = out + ((size_t)b * N_ + i) * C_;
        op[lane] = v0;
        op[lane + 32] = v1;
    }
}

// ---------------------------------------------------------------------------
extern "C" void kernel_launch(void* const* d_in, const int* in_sizes, int n_in,
                              void* d_out, int out_size) {
    const float* input = (const float*)d_in[0];  // (32,1024,64)
    const float* adj   = (const float*)d_in[1];  // (1024,1024)
    const float* W     = (const float*)d_in[2];  // (64,64)
    const float* a     = (const float*)d_in[3];  // (128,1)
    float* out = (float*)d_out;

    gemm_h_kernel<<<BN / 64, 256>>>(input, W);
    dots_kernel<<<BN / 8, 256>>>(a);
    attn_kernel<<<dim3(N_ / 64, B_), 256>>>(adj, out);
}

// round 3
// speedup vs baseline: 1.4761x; 1.4761x over previous
#include <cuda_runtime.h>
#include <cstdint>
#include <math.h>

#define B_ 32
#define N_ 1024
#define C_ 64
#define BN (B_ * N_)

// device-global scratch (allocation-free rule)
__device__ float g_h[BN * C_];
__device__ float g_ssrc[BN];
__device__ float g_sdst[BN];
__device__ float g_smax[B_];

__device__ __forceinline__ uint32_t tf32r(float v) {
    uint32_t r; asm("cvt.rna.tf32.f32 %0, %1;" : "=r"(r) : "f"(v)); return r;
}

__device__ __forceinline__ void mma_tf32(float* d,
                                         uint32_t a0, uint32_t a1, uint32_t a2, uint32_t a3,
                                         uint32_t b0, uint32_t b1) {
    asm volatile(
        "mma.sync.aligned.m16n8k8.row.col.f32.tf32.tf32.f32 "
        "{%0,%1,%2,%3},{%4,%5,%6,%7},{%8,%9},{%0,%1,%2,%3};"
        : "+f"(d[0]), "+f"(d[1]), "+f"(d[2]), "+f"(d[3])
        : "r"(a0), "r"(a1), "r"(a2), "r"(a3), "r"(b0), "r"(b1));
}

// ---------------------------------------------------------------------------
// Kernel A: h = input @ W   (row-major g_h)
// ---------------------------------------------------------------------------
__global__ void __launch_bounds__(256) gemm_h_kernel(const float* __restrict__ in,
                                                     const float* __restrict__ W) {
    __shared__ float Ws[64 * 64];
    __shared__ float Is[64 * 64];
    const int t = threadIdx.x;
    const int row0 = blockIdx.x * 64;

    const float4* W4 = (const float4*)W;
    float4* Ws4 = (float4*)Ws;
#pragma unroll
    for (int q = 0; q < 4; q++) Ws4[t + q * 256] = W4[t + q * 256];
    const float4* in4 = (const float4*)(in + row0 * 64);
    float4* Is4 = (float4*)Is;
#pragma unroll
    for (int q = 0; q < 4; q++) Is4[t + q * 256] = in4[t + q * 256];
    __syncthreads();

    const int c = t & 63;
    const int r0 = t >> 6;
    float acc[16];
#pragma unroll
    for (int q = 0; q < 16; q++) acc[q] = 0.0f;
#pragma unroll
    for (int k = 0; k < 64; k++) {
        float w = Ws[k * 64 + c];
#pragma unroll
        for (int q = 0; q < 16; q++)
            acc[q] = fmaf(Is[(r0 + 4 * q) * 64 + k], w, acc[q]);
    }
#pragma unroll
    for (int q = 0; q < 16; q++)
        g_h[(row0 + r0 + 4 * q) * 64 + c] = acc[q];
}

// ---------------------------------------------------------------------------
// Kernel B: s_src / s_dst (one warp per row)
// ---------------------------------------------------------------------------
__global__ void __launch_bounds__(256) dots_kernel(const float* __restrict__ a) {
    const int row = blockIdx.x * 8 + (threadIdx.x >> 5);
    const int lane = threadIdx.x & 31;
    const float* hr = g_h + row * 64;
    float h0 = hr[lane], h1 = hr[lane + 32];
    float ss = h0 * a[lane] + h1 * a[lane + 32];
    float sd = h0 * a[64 + lane] + h1 * a[96 + lane];
#pragma unroll
    for (int o = 16; o; o >>= 1) {
        ss += __shfl_xor_sync(0xffffffffu, ss, o);
        sd += __shfl_xor_sync(0xffffffffu, sd, o);
    }
    if (lane == 0) {
        g_ssrc[row] = ss;
        g_sdst[row] = sd;
    }
}

// ---------------------------------------------------------------------------
// Kernel C: per-batch max of sdst
// ---------------------------------------------------------------------------
__global__ void __launch_bounds__(256) smax_kernel() {
    __shared__ float red[8];
    const int b = blockIdx.x, t = threadIdx.x;
    float v = -INFINITY;
#pragma unroll
    for (int k = 0; k < 4; k++) v = fmaxf(v, g_sdst[b * 1024 + t + k * 256]);
#pragma unroll
    for (int o = 16; o; o >>= 1) v = fmaxf(v, __shfl_xor_sync(0xffffffffu, v, o));
    if ((t & 31) == 0) red[t >> 5] = v;
    __syncthreads();
    if (t == 0) {
        float m = red[0];
#pragma unroll
        for (int i = 1; i < 8; i++) m = fmaxf(m, red[i]);
        g_smax[b] = m;
    }
}

// ---------------------------------------------------------------------------
// Kernel D: fused attention. Scores in fp32 registers directly in the
// m16n8k8 A-fragment layout; PV via mma.sync 3xTF32; D accumulates in regs.
// Block = (i-tile 128, batch). 8 warps; warp w owns rows i0+16w..+16.
// ---------------------------------------------------------------------------
#define HS 72  // padded smem stride (conflict-free B-fragment LDS)

__global__ void __launch_bounds__(256, 2) attn_kernel(const float* __restrict__ adj,
                                                      float* __restrict__ out) {
    __shared__ uint32_t h_hi[64 * HS];
    __shared__ uint32_t h_lo[64 * HS];
    __shared__ float sdst_s[64];

    const int b = blockIdx.y;
    const int i0 = blockIdx.x * 128;
    const int t = threadIdx.x;
    const int w = t >> 5;
    const int lane = t & 31;
    const int r0 = lane >> 2;   // group id
    const int c0 = lane & 3;    // thread-in-group

    const int irow0 = i0 + w * 16 + r0;
    const int irow1 = irow0 + 8;

    const float S = g_smax[b];
    const float ss0 = g_ssrc[b * N_ + irow0];
    const float ss1 = g_ssrc[b * N_ + irow1];
    float mm0 = ss0 + S; mm0 = mm0 >= 0.f ? mm0 : 0.2f * mm0;
    float mm1 = ss1 + S; mm1 = mm1 >= 0.f ? mm1 : 0.2f * mm1;
    float l0 = 0.f, l1 = 0.f;

    float D[8][4];
#pragma unroll
    for (int nb = 0; nb < 8; nb++)
#pragma unroll
        for (int q = 0; q < 4; q++) D[nb][q] = 0.f;

    const float* hb = g_h + (size_t)b * N_ * C_;
    const float* adj0 = adj + (size_t)irow0 * N_;
    const float* adj1 = adj + (size_t)irow1 * N_;

    for (int jt = 0; jt < 16; jt++) {
        const int j0 = jt * 64;
        __syncthreads();  // previous tile's readers done
        // stage h tile -> hi/lo tf32, stride HS
#pragma unroll
        for (int k = 0; k < 16; k++) {
            int e = t + k * 256;
            int j = e >> 6, c = e & 63;
            float v = hb[(j0 + j) * 64 + c];
            uint32_t hi = tf32r(v);
            uint32_t lo = tf32r(v - __uint_as_float(hi));
            h_hi[j * HS + c] = hi;
            h_lo[j * HS + c] = lo;
        }
        if (t < 64) sdst_s[t] = g_sdst[b * N_ + j0 + t];
        __syncthreads();

#pragma unroll
        for (int kk = 0; kk < 8; kk++) {
            const int jA = kk * 8 + c0;
            const int jB = jA + 4;
            const float sdA = sdst_s[jA];
            const float sdB = sdst_s[jB];

            // adj gate loads (L2-resident, batched by unroll for MLP)
            const float gA0 = __ldg(adj0 + j0 + jA);
            const float gA1 = __ldg(adj1 + j0 + jA);
            const float gB0 = __ldg(adj0 + j0 + jB);
            const float gB1 = __ldg(adj1 + j0 + jB);

            float x;
            x = ss0 + sdA; x = x >= 0.f ? x : 0.2f * x;
            const float p0 = gA0 > 0.5f ? __expf(x - mm0) : 0.f;
            x = ss1 + sdA; x = x >= 0.f ? x : 0.2f * x;
            const float p1 = gA1 > 0.5f ? __expf(x - mm1) : 0.f;
            x = ss0 + sdB; x = x >= 0.f ? x : 0.2f * x;
            const float p2 = gB0 > 0.5f ? __expf(x - mm0) : 0.f;
            x = ss1 + sdB; x = x >= 0.f ? x : 0.2f * x;
            const float p3 = gB1 > 0.5f ? __expf(x - mm1) : 0.f;

            l0 += p0 + p2;
            l1 += p1 + p3;

            const uint32_t ah0 = tf32r(p0), ah1 = tf32r(p1), ah2 = tf32r(p2), ah3 = tf32r(p3);
            const uint32_t al0 = tf32r(p0 - __uint_as_float(ah0));
            const uint32_t al1 = tf32r(p1 - __uint_as_float(ah1));
            const uint32_t al2 = tf32r(p2 - __uint_as_float(ah2));
            const uint32_t al3 = tf32r(p3 - __uint_as_float(ah3));

            const uint32_t* bh = h_hi + (kk * 8 + c0) * HS;
            const uint32_t* bl = h_lo + (kk * 8 + c0) * HS;
#pragma unroll
            for (int nb = 0; nb < 8; nb++) {
                const int col = nb * 8 + r0;
                const uint32_t bh0 = bh[col];
                const uint32_t bh1 = bh[4 * HS + col];
                const uint32_t bl0 = bl[col];
                const uint32_t bl1 = bl[4 * HS + col];
                mma_tf32(D[nb], ah0, ah1, ah2, ah3, bh0, bh1);
                mma_tf32(D[nb], ah0, ah1, ah2, ah3, bl0, bl1);
                mma_tf32(D[nb], al0, al1, al2, al3, bh0, bh1);
            }
        }
    }

    // reduce softmax denominators across the quad owning each row
    l0 += __shfl_xor_sync(0xffffffffu, l0, 1);
    l0 += __shfl_xor_sync(0xffffffffu, l0, 2);
    l1 += __shfl_xor_sync(0xffffffffu, l1, 1);
    l1 += __shfl_xor_sync(0xffffffffu, l1, 2);
    const float inv0 = 1.0f / l0;
    const float inv1 = 1.0f / l1;

    // epilogue: normalize + ELU, float2 stores (32B per quad per nb)
    float2* o0 = (float2*)(out + ((size_t)b * N_ + irow0) * C_ + 2 * c0);
    float2* o1 = (float2*)(out + ((size_t)b * N_ + irow1) * C_ + 2 * c0);
#pragma unroll
    for (int nb = 0; nb < 8; nb++) {
        float v0 = D[nb][0] * inv0;
        float v1 = D[nb][1] * inv0;
        float v2 = D[nb][2] * inv1;
        float v3 = D[nb][3] * inv1;
        v0 = v0 > 0.f ? v0 : (__expf(v0) - 1.0f);
        v1 = v1 > 0.f ? v1 : (__expf(v1) - 1.0f);
        v2 = v2 > 0.f ? v2 : (__expf(v2) - 1.0f);
        v3 = v3 > 0.f ? v3 : (__expf(v3) - 1.0f);
        o0[nb * 4] = make_float2(v0, v1);
        o1[nb * 4] = make_float2(v2, v3);
    }
}

// ---------------------------------------------------------------------------
extern "C" void kernel_launch(void* const* d_in, const int* in_sizes, int n_in,
                              void* d_out, int out_size) {
    const float* input = (const float*)d_in[0];  // (32,1024,64)
    const float* adj   = (const float*)d_in[1];  // (1024,1024)
    const float* W     = (const float*)d_in[2];  // (64,64)
    const float* a     = (const float*)d_in[3];  // (128,1)
    float* out = (float*)d_out;

    gemm_h_kernel<<<BN / 64, 256>>>(input, W);
    dots_kernel<<<BN / 8, 256>>>(a);
    smax_kernel<<<B_, 256>>>();
    attn_kernel<<<dim3(N_ / 128, B_), 256>>>(adj, out);
}

// round 7
// speedup vs baseline: 1.6110x; 1.0914x over previous
#include <cuda_runtime.h>
#include <cstdint>
#include <math.h>

#define B_ 32
#define N_ 1024
#define C_ 64
#define BN (B_ * N_)

// device-global scratch (allocation-free rule)
__device__ float  g_h[BN * C_];
__device__ float2 g_hpair[BN * C_];      // (tf32_hi, residual_lo) per h element
__device__ float  g_ssrc[BN];
__device__ float  g_sdst[BN];
__device__ float  g_smax[B_];
__device__ uint32_t g_mask[N_ * N_ / 32]; // adj>0.5 bitmask, [i][j/32]

__device__ __forceinline__ uint32_t smem_u32(const void* p) {
    uint32_t a;
    asm("{ .reg .u64 t; cvta.to.shared.u64 t, %1; cvt.u32.u64 %0, t; }" : "=r"(a) : "l"(p));
    return a;
}
__device__ __forceinline__ float tf32_hi(float v) {
    return __uint_as_float(__float_as_uint(v) & 0xFFFFE000u);
}
__device__ __forceinline__ void cp_async16(uint32_t dst, const void* src) {
    asm volatile("cp.async.cg.shared.global [%0], [%1], 16;" :: "r"(dst), "l"(src));
}
#define CP_COMMIT() asm volatile("cp.async.commit_group;" ::: "memory")
#define CP_WAIT1()  asm volatile("cp.async.wait_group 1;" ::: "memory")

__device__ __forceinline__ void mma_tf32(float* d,
                                         float a0, float a1, float a2, float a3,
                                         uint32_t b0, uint32_t b1) {
    asm volatile(
        "mma.sync.aligned.m16n8k8.row.col.f32.tf32.tf32.f32 "
        "{%0,%1,%2,%3},{%4,%5,%6,%7},{%8,%9},{%0,%1,%2,%3};"
        : "+f"(d[0]), "+f"(d[1]), "+f"(d[2]), "+f"(d[3])
        : "r"(__float_as_uint(a0)), "r"(__float_as_uint(a1)),
          "r"(__float_as_uint(a2)), "r"(__float_as_uint(a3)), "r"(b0), "r"(b1));
}

// ---------------------------------------------------------------------------
// Kernel M: adj > 0.5 bitmask via warp ballot (coalesced reads).
// 8192 warps total, each covers 128 consecutive adj elements (4 mask words).
// ---------------------------------------------------------------------------
__global__ void __launch_bounds__(256) mask_kernel(const float* __restrict__ adj) {
    const int gw = (blockIdx.x * 256 + threadIdx.x) >> 5;  // 0..8191
    const int lane = threadIdx.x & 31;
    const float* base = adj + (size_t)gw * 128;
#pragma unroll
    for (int q = 0; q < 4; q++) {
        float v = __ldg(base + q * 32 + lane);
        uint32_t m = __ballot_sync(0xffffffffu, v > 0.5f);
        if (lane == 0) g_mask[gw * 4 + q] = m;
    }
}

// ---------------------------------------------------------------------------
// Kernel A: h = input @ W. 4x4 register tile per thread. Also writes the
// tf32 hi/lo split pair array used by the attention MMA.
// ---------------------------------------------------------------------------
__global__ void __launch_bounds__(256) gemm_h_kernel(const float* __restrict__ in,
                                                     const float* __restrict__ W) {
    __shared__ float Ws[64 * 64];
    __shared__ float Is[64 * 64];
    const int t = threadIdx.x;
    const int row0 = blockIdx.x * 64;

    const float4* W4 = (const float4*)W;
    float4* Ws4 = (float4*)Ws;
#pragma unroll
    for (int q = 0; q < 4; q++) Ws4[t + q * 256] = W4[t + q * 256];
    const float4* in4 = (const float4*)(in + row0 * 64);
    float4* Is4 = (float4*)Is;
#pragma unroll
    for (int q = 0; q < 4; q++) Is4[t + q * 256] = in4[t + q * 256];
    __syncthreads();

    const int tx = t & 15;
    const int ty = t >> 4;
    float acc[4][4];
#pragma unroll
    for (int i = 0; i < 4; i++)
#pragma unroll
        for (int j = 0; j < 4; j++) acc[i][j] = 0.f;

#pragma unroll
    for (int k = 0; k < 64; k++) {
        const float4 b = *(const float4*)&Ws[k * 64 + 4 * tx];
        const float a0 = Is[(4 * ty + 0) * 64 + k];
        const float a1 = Is[(4 * ty + 1) * 64 + k];
        const float a2 = Is[(4 * ty + 2) * 64 + k];
        const float a3 = Is[(4 * ty + 3) * 64 + k];
        acc[0][0] = fmaf(a0, b.x, acc[0][0]); acc[0][1] = fmaf(a0, b.y, acc[0][1]);
        acc[0][2] = fmaf(a0, b.z, acc[0][2]); acc[0][3] = fmaf(a0, b.w, acc[0][3]);
        acc[1][0] = fmaf(a1, b.x, acc[1][0]); acc[1][1] = fmaf(a1, b.y, acc[1][1]);
        acc[1][2] = fmaf(a1, b.z, acc[1][2]); acc[1][3] = fmaf(a1, b.w, acc[1][3]);
        acc[2][0] = fmaf(a2, b.x, acc[2][0]); acc[2][1] = fmaf(a2, b.y, acc[2][1]);
        acc[2][2] = fmaf(a2, b.z, acc[2][2]); acc[2][3] = fmaf(a2, b.w, acc[2][3]);
        acc[3][0] = fmaf(a3, b.x, acc[3][0]); acc[3][1] = fmaf(a3, b.y, acc[3][1]);
        acc[3][2] = fmaf(a3, b.z, acc[3][2]); acc[3][3] = fmaf(a3, b.w, acc[3][3]);
    }

#pragma unroll
    for (int i = 0; i < 4; i++) {
        const int row = row0 + 4 * ty + i;
        *(float4*)&g_h[(size_t)row * 64 + 4 * tx] =
            make_float4(acc[i][0], acc[i][1], acc[i][2], acc[i][3]);
        float2 hp[4];
#pragma unroll
        for (int j = 0; j < 4; j++) {
            float hi = tf32_hi(acc[i][j]);
            hp[j] = make_float2(hi, acc[i][j] - hi);
        }
        float2* pd = &g_hpair[(size_t)row * 64 + 4 * tx];
        *(float4*)&pd[0] = *(float4*)&hp[0];
        *(float4*)&pd[2] = *(float4*)&hp[2];
    }
}

// ---------------------------------------------------------------------------
// Kernel B: s_src / s_dst (one warp per row)
// ---------------------------------------------------------------------------
__global__ void __launch_bounds__(256) dots_kernel(const float* __restrict__ a) {
    const int row = blockIdx.x * 8 + (threadIdx.x >> 5);
    const int lane = threadIdx.x & 31;
    const float* hr = g_h + (size_t)row * 64;
    float h0 = hr[lane], h1 = hr[lane + 32];
    float ss = h0 * a[lane] + h1 * a[lane + 32];
    float sd = h0 * a[64 + lane] + h1 * a[96 + lane];
#pragma unroll
    for (int o = 16; o; o >>= 1) {
        ss += __shfl_xor_sync(0xffffffffu, ss, o);
        sd += __shfl_xor_sync(0xffffffffu, sd, o);
    }
    if (lane == 0) {
        g_ssrc[row] = ss;
        g_sdst[row] = sd;
    }
}

// ---------------------------------------------------------------------------
// Kernel C: per-batch max of sdst
// ---------------------------------------------------------------------------
__global__ void __launch_bounds__(256) smax_kernel() {
    __shared__ float red[8];
    const int b = blockIdx.x, t = threadIdx.x;
    float v = -INFINITY;
#pragma unroll
    for (int k = 0; k < 4; k++) v = fmaxf(v, g_sdst[b * 1024 + t + k * 256]);
#pragma unroll
    for (int o = 16; o; o >>= 1) v = fmaxf(v, __shfl_xor_sync(0xffffffffu, v, o));
    if ((t & 31) == 0) red[t >> 5] = v;
    __syncthreads();
    if (t == 0) {
        float m = red[0];
#pragma unroll
        for (int i = 1; i < 8; i++) m = fmaxf(m, red[i]);
        g_smax[b] = m;
    }
}

// ---------------------------------------------------------------------------
// Kernel D: fused attention. cp.async double-buffered h-pair tiles; adj gates
// from bitmask (4 words/thread/tile, prefetched); PV via mma.sync 3xTF32.
// ---------------------------------------------------------------------------
#define PSTRIDE 68                          // float2 stride per j-row (pad 4)
#define PAIR_BYTES (64 * PSTRIDE * 8)       // 34816
#define OFF_P0 0
#define OFF_P1 PAIR_BYTES
#define OFF_S0 (2 * PAIR_BYTES)
#define OFF_S1 (2 * PAIR_BYTES + 256)
#define SMEM_DYN (2 * PAIR_BYTES + 512)

__global__ void __launch_bounds__(256, 2) attn_kernel(float* __restrict__ out) {
    extern __shared__ char sm[];
    const uint32_t smb = smem_u32(sm);

    const int b = blockIdx.y;
    const int i0 = blockIdx.x * 128;
    const int t = threadIdx.x;
    const int w = t >> 5;
    const int lane = t & 31;
    const int r0 = lane >> 2;
    const int c0 = lane & 3;

    const int irow0 = i0 + w * 16 + r0;
    const int irow1 = irow0 + 8;

    const float S = g_smax[b];
    const float ss0 = g_ssrc[b * N_ + irow0];
    const float ss1 = g_ssrc[b * N_ + irow1];
    float mm0 = ss0 + S; mm0 = mm0 >= 0.f ? mm0 : 0.2f * mm0;
    float mm1 = ss1 + S; mm1 = mm1 >= 0.f ? mm1 : 0.2f * mm1;
    float l0 = 0.f, l1 = 0.f;

    float D[8][4];
#pragma unroll
    for (int nb = 0; nb < 8; nb++)
#pragma unroll
        for (int q = 0; q < 4; q++) D[nb][q] = 0.f;

    const float2* hp = g_hpair + (size_t)b * N_ * C_;
    const float* sdsrc = g_sdst + b * N_;
    const uint32_t* mk0 = g_mask + (size_t)irow0 * 32;  // 32 words per row
    const uint32_t* mk1 = g_mask + (size_t)irow1 * 32;

    // ---- tile staging via cp.async -------------------------------------
    auto stage = [&](int jt) {
        const uint32_t pb = smb + ((jt & 1) ? OFF_P1 : OFF_P0);
        const float2* src = hp + jt * 64 * 64;
#pragma unroll
        for (int q = 0; q < 8; q++) {
            const int cid = q * 256 + t;          // 16B chunk id (2048 total)
            const int row = cid >> 5;
            const int cc = (cid & 31) * 2;        // float2 col
            cp_async16(pb + (uint32_t)(row * PSTRIDE + cc) * 8u, src + row * 64 + cc);
        }
        if (t < 16)  // 16 x 16B = 64 floats (FIX: was t<4, leaving 48 floats garbage)
            cp_async16(smb + ((jt & 1) ? OFF_S1 : OFF_S0) + t * 16u, sdsrc + jt * 64 + t * 4);
    };

    stage(0); CP_COMMIT();
    stage(1); CP_COMMIT();

    // gate mask words for tile 0 (quad-uniform -> L1 broadcast)
    uint32_t mw00 = __ldg(mk0 + 0), mw01 = __ldg(mk0 + 1);
    uint32_t mw10 = __ldg(mk1 + 0), mw11 = __ldg(mk1 + 1);

    for (int jt = 0; jt < 16; jt++) {
        CP_WAIT1();
        __syncthreads();

        // prefetch next tile's mask words
        const int jw = (jt < 15) ? (jt + 1) * 2 : 0;
        const uint32_t nw00 = __ldg(mk0 + jw), nw01 = __ldg(mk0 + jw + 1);
        const uint32_t nw10 = __ldg(mk1 + jw), nw11 = __ldg(mk1 + jw + 1);

        const uint2* pairs = (const uint2*)(sm + ((jt & 1) ? OFF_P1 : OFF_P0));
        const float* sds = (const float*)(sm + ((jt & 1) ? OFF_S1 : OFF_S0));

#pragma unroll
        for (int kk = 0; kk < 8; kk++) {
            const int jA = kk * 8 + c0;
            const int jB = jA + 4;
            const uint32_t w0 = (kk < 4) ? mw00 : mw01;  // gates row irow0
            const uint32_t w1 = (kk < 4) ? mw10 : mw11;  // gates row irow1
            const int bA = jA & 31, bB = jB & 31;

            const float sdA = sds[jA];
            const float sdB = sds[jB];

            float x;
            x = ss0 + sdA; x = x >= 0.f ? x : 0.2f * x;
            const float p0 = ((w0 >> bA) & 1u) ? __expf(x - mm0) : 0.f;
            x = ss1 + sdA; x = x >= 0.f ? x : 0.2f * x;
            const float p1 = ((w1 >> bA) & 1u) ? __expf(x - mm1) : 0.f;
            x = ss0 + sdB; x = x >= 0.f ? x : 0.2f * x;
            const float p2 = ((w0 >> bB) & 1u) ? __expf(x - mm0) : 0.f;
            x = ss1 + sdB; x = x >= 0.f ? x : 0.2f * x;
            const float p3 = ((w1 >> bB) & 1u) ? __expf(x - mm1) : 0.f;

            l0 += p0 + p2;
            l1 += p1 + p3;

            const float ph0 = tf32_hi(p0), ph1 = tf32_hi(p1);
            const float ph2 = tf32_hi(p2), ph3 = tf32_hi(p3);
            const float pl0 = p0 - ph0, pl1 = p1 - ph1;
            const float pl2 = p2 - ph2, pl3 = p3 - ph3;

            const uint2* bp = pairs + (kk * 8 + c0) * PSTRIDE + r0;
#pragma unroll
            for (int nb = 0; nb < 8; nb++) {
                const uint2 x0 = bp[nb * 8];                 // (hi, lo) at k0
                const uint2 x1 = bp[4 * PSTRIDE + nb * 8];   // (hi, lo) at k0+4
                mma_tf32(D[nb], ph0, ph1, ph2, ph3, x0.x, x1.x);
                mma_tf32(D[nb], ph0, ph1, ph2, ph3, x0.y, x1.y);
                mma_tf32(D[nb], pl0, pl1, pl2, pl3, x0.x, x1.x);
            }
        }

        __syncthreads();
        if (jt + 2 < 16) stage(jt + 2);
        CP_COMMIT();

        mw00 = nw00; mw01 = nw01; mw10 = nw10; mw11 = nw11;
    }

    // reduce softmax denominators across the quad owning each row
    l0 += __shfl_xor_sync(0xffffffffu, l0, 1);
    l0 += __shfl_xor_sync(0xffffffffu, l0, 2);
    l1 += __shfl_xor_sync(0xffffffffu, l1, 1);
    l1 += __shfl_xor_sync(0xffffffffu, l1, 2);
    const float inv0 = 1.0f / l0;
    const float inv1 = 1.0f / l1;

    float2* o0 = (float2*)(out + ((size_t)b * N_ + irow0) * C_ + 2 * c0);
    float2* o1 = (float2*)(out + ((size_t)b * N_ + irow1) * C_ + 2 * c0);
#pragma unroll
    for (int nb = 0; nb < 8; nb++) {
        float v0 = D[nb][0] * inv0;
        float v1 = D[nb][1] * inv0;
        float v2 = D[nb][2] * inv1;
        float v3 = D[nb][3] * inv1;
        v0 = v0 > 0.f ? v0 : (__expf(v0) - 1.0f);
        v1 = v1 > 0.f ? v1 : (__expf(v1) - 1.0f);
        v2 = v2 > 0.f ? v2 : (__expf(v2) - 1.0f);
        v3 = v3 > 0.f ? v3 : (__expf(v3) - 1.0f);
        o0[nb * 4] = make_float2(v0, v1);
        o1[nb * 4] = make_float2(v2, v3);
    }
}

// ---------------------------------------------------------------------------
extern "C" void kernel_launch(void* const* d_in, const int* in_sizes, int n_in,
                              void* d_out, int out_size) {
    const float* input = (const float*)d_in[0];  // (32,1024,64)
    const float* adj   = (const float*)d_in[1];  // (1024,1024)
    const float* W     = (const float*)d_in[2];  // (64,64)
    const float* a     = (const float*)d_in[3];  // (128,1)
    float* out = (float*)d_out;

    cudaFuncSetAttribute(attn_kernel, cudaFuncAttributeMaxDynamicSharedMemorySize, SMEM_DYN);

    // 8192 warps x 128 elements = 1M adj entries -> 1024 blocks of 256
    mask_kernel<<<N_ * N_ / (128 * 8), 256>>>(adj);
    gemm_h_kernel<<<BN / 64, 256>>>(input, W);
    dots_kernel<<<BN / 8, 256>>>(a);
    smax_kernel<<<B_, 256>>>();
    attn_kernel<<<dim3(N_ / 128, B_), 256, SMEM_DYN>>>(out);
}

// round 8
// speedup vs baseline: 2.4835x; 1.5416x over previous
#include <cuda_runtime.h>
#include <cuda_fp16.h>
#include <cstdint>
#include <math.h>

#define B_ 32
#define N_ 1024
#define C_ 64
#define BN (B_ * N_)

// device-global scratch (allocation-free rule)
__device__ float  g_h[BN * C_];
__device__ uint2  g_hpk[B_ * C_ * (N_ / 2)];  // [b][c][npair]: (hh2, hl2) packed fp16 pairs
__device__ float  g_ssrc[BN];
__device__ float  g_sdst[BN];
__device__ float4 g_ABT[BN];                  // (A, B, TE, -) per row
__device__ float2 g_EF[BN];                   // (E, F) per col
__device__ uint32_t g_mask[N_ * N_ / 32];     // adj>0.5 bitmask

__device__ __forceinline__ uint32_t smem_u32(const void* p) {
    uint32_t a;
    asm("{ .reg .u64 t; cvta.to.shared.u64 t, %1; cvt.u32.u64 %0, t; }" : "=r"(a) : "l"(p));
    return a;
}
__device__ __forceinline__ void cp_async16(uint32_t dst, const void* src) {
    asm volatile("cp.async.cg.shared.global [%0], [%1], 16;" :: "r"(dst), "l"(src));
}
#define CP_COMMIT() asm volatile("cp.async.commit_group;" ::: "memory")
#define CP_WAIT1()  asm volatile("cp.async.wait_group 1;" ::: "memory")

__device__ __forceinline__ void mma_f16(float* d,
                                        uint32_t a0, uint32_t a1, uint32_t a2, uint32_t a3,
                                        uint32_t b0, uint32_t b1) {
    asm volatile(
        "mma.sync.aligned.m16n8k16.row.col.f32.f16.f16.f32 "
        "{%0,%1,%2,%3},{%4,%5,%6,%7},{%8,%9},{%0,%1,%2,%3};"
        : "+f"(d[0]), "+f"(d[1]), "+f"(d[2]), "+f"(d[3])
        : "r"(a0), "r"(a1), "r"(a2), "r"(a3), "r"(b0), "r"(b1));
}
__device__ __forceinline__ uint32_t h2u(__half2 h) { return *(uint32_t*)&h; }

// ---------------------------------------------------------------------------
// Kernel M: adj > 0.5 bitmask via warp ballot
// ---------------------------------------------------------------------------
__global__ void __launch_bounds__(256) mask_kernel(const float* __restrict__ adj) {
    const int gw = (blockIdx.x * 256 + threadIdx.x) >> 5;  // 0..8191
    const int lane = threadIdx.x & 31;
    const float* base = adj + (size_t)gw * 128;
#pragma unroll
    for (int q = 0; q < 4; q++) {
        float v = __ldg(base + q * 32 + lane);
        uint32_t m = __ballot_sync(0xffffffffu, v > 0.5f);
        if (lane == 0) g_mask[gw * 4 + q] = m;
    }
}

// ---------------------------------------------------------------------------
// Kernel A: h = input @ W. 4x4 register tile. Writes g_h (for dots) and the
// packed fp16 hi/lo B-operand array g_hpk[b][c][npair] = (hh2, hl2).
// ---------------------------------------------------------------------------
__global__ void __launch_bounds__(256) gemm_h_kernel(const float* __restrict__ in,
                                                     const float* __restrict__ W) {
    __shared__ float Ws[64 * 64];
    __shared__ float Is[64 * 64];
    const int t = threadIdx.x;
    const int row0 = blockIdx.x * 64;

    const float4* W4 = (const float4*)W;
    float4* Ws4 = (float4*)Ws;
#pragma unroll
    for (int q = 0; q < 4; q++) Ws4[t + q * 256] = W4[t + q * 256];
    const float4* in4 = (const float4*)(in + row0 * 64);
    float4* Is4 = (float4*)Is;
#pragma unroll
    for (int q = 0; q < 4; q++) Is4[t + q * 256] = in4[t + q * 256];
    __syncthreads();

    const int tx = t & 15;
    const int ty = t >> 4;
    float acc[4][4];
#pragma unroll
    for (int i = 0; i < 4; i++)
#pragma unroll
        for (int j = 0; j < 4; j++) acc[i][j] = 0.f;

#pragma unroll
    for (int k = 0; k < 64; k++) {
        const float4 b = *(const float4*)&Ws[k * 64 + 4 * tx];
        const float a0 = Is[(4 * ty + 0) * 64 + k];
        const float a1 = Is[(4 * ty + 1) * 64 + k];
        const float a2 = Is[(4 * ty + 2) * 64 + k];
        const float a3 = Is[(4 * ty + 3) * 64 + k];
        acc[0][0] = fmaf(a0, b.x, acc[0][0]); acc[0][1] = fmaf(a0, b.y, acc[0][1]);
        acc[0][2] = fmaf(a0, b.z, acc[0][2]); acc[0][3] = fmaf(a0, b.w, acc[0][3]);
        acc[1][0] = fmaf(a1, b.x, acc[1][0]); acc[1][1] = fmaf(a1, b.y, acc[1][1]);
        acc[1][2] = fmaf(a1, b.z, acc[1][2]); acc[1][3] = fmaf(a1, b.w, acc[1][3]);
        acc[2][0] = fmaf(a2, b.x, acc[2][0]); acc[2][1] = fmaf(a2, b.y, acc[2][1]);
        acc[2][2] = fmaf(a2, b.z, acc[2][2]); acc[2][3] = fmaf(a2, b.w, acc[2][3]);
        acc[3][0] = fmaf(a3, b.x, acc[3][0]); acc[3][1] = fmaf(a3, b.y, acc[3][1]);
        acc[3][2] = fmaf(a3, b.z, acc[3][2]); acc[3][3] = fmaf(a3, b.w, acc[3][3]);
    }

    const int b = row0 >> 10;
    const int n0 = row0 & 1023;
#pragma unroll
    for (int i = 0; i < 4; i++) {
        const int row = row0 + 4 * ty + i;
        *(float4*)&g_h[(size_t)row * 64 + 4 * tx] =
            make_float4(acc[i][0], acc[i][1], acc[i][2], acc[i][3]);
    }
    // packed fp16 hi/lo pairs along n (rows 4ty+{0,1} and {2,3} pair in-thread)
#pragma unroll
    for (int p = 0; p < 2; p++) {
        const int npair = (n0 + 4 * ty) / 2 + p;  // global n-pair within batch
#pragma unroll
        for (int j = 0; j < 4; j++) {
            const float va = acc[2 * p + 0][j];
            const float vb = acc[2 * p + 1][j];
            const __half ha = __float2half_rn(va);
            const __half hb = __float2half_rn(vb);
            const float ra = va - __half2float(ha);
            const float rb = vb - __half2float(hb);
            uint2 pk;
            __half2 hh = __halves2half2(ha, hb);
            __half2 hl = __floats2half2_rn(ra, rb);
            pk.x = h2u(hh);
            pk.y = h2u(hl);
            g_hpk[((size_t)b * 64 + 4 * tx + j) * 512 + npair] = pk;
        }
    }
}

// ---------------------------------------------------------------------------
// Kernel B: s_src / s_dst (one warp per row)
// ---------------------------------------------------------------------------
__global__ void __launch_bounds__(256) dots_kernel(const float* __restrict__ a) {
    const int row = blockIdx.x * 8 + (threadIdx.x >> 5);
    const int lane = threadIdx.x & 31;
    const float* hr = g_h + (size_t)row * 64;
    float h0 = hr[lane], h1 = hr[lane + 32];
    float ss = h0 * a[lane] + h1 * a[lane + 32];
    float sd = h0 * a[64 + lane] + h1 * a[96 + lane];
#pragma unroll
    for (int o = 16; o; o >>= 1) {
        ss += __shfl_xor_sync(0xffffffffu, ss, o);
        sd += __shfl_xor_sync(0xffffffffu, sd, o);
    }
    if (lane == 0) {
        g_ssrc[row] = ss;
        g_sdst[row] = sd;
    }
}

// ---------------------------------------------------------------------------
// Kernel C: per-batch max + factored-softmax coefficients
//   m_i = lrelu(ss_i + S);  A=exp(ss-m), B=exp(.2ss-m), TE=exp(-ss)
//   E_j = exp(sd_j), F_j = exp(.2 sd_j)
// ---------------------------------------------------------------------------
__global__ void __launch_bounds__(256) prep_kernel() {
    __shared__ float red[8];
    __shared__ float Ssh;
    const int b = blockIdx.x, t = threadIdx.x;
    float v = -INFINITY;
#pragma unroll
    for (int k = 0; k < 4; k++) v = fmaxf(v, g_sdst[b * 1024 + t + k * 256]);
#pragma unroll
    for (int o = 16; o; o >>= 1) v = fmaxf(v, __shfl_xor_sync(0xffffffffu, v, o));
    if ((t & 31) == 0) red[t >> 5] = v;
    __syncthreads();
    if (t == 0) {
        float m = red[0];
#pragma unroll
        for (int i = 1; i < 8; i++) m = fmaxf(m, red[i]);
        Ssh = m;
    }
    __syncthreads();
    const float S = Ssh;
#pragma unroll
    for (int k = 0; k < 4; k++) {
        const int idx = b * 1024 + t + k * 256;
        const float ss = g_ssrc[idx];
        const float sd = g_sdst[idx];
        float mm = ss + S; mm = mm >= 0.f ? mm : 0.2f * mm;
        g_ABT[idx] = make_float4(__expf(ss - mm), __expf(0.2f * ss - mm), __expf(-ss), 0.f);
        g_EF[idx] = make_float2(__expf(sd), __expf(0.2f * sd));
    }
}

// ---------------------------------------------------------------------------
// Kernel D: fused attention. Factored exp (no MUFU in loop), bitmask gates,
// cp.async double-buffered packed-fp16 tiles, PV via 3xFP16 mma m16n8k16.
// ---------------------------------------------------------------------------
#define PKS 36  // uint2 stride per c-row (32 kpairs + pad 4; 4q+kp conflict-free)

__global__ void __launch_bounds__(256, 2) attn_kernel(float* __restrict__ out) {
    __shared__ uint2  pk[2][64 * PKS];
    __shared__ float2 ef[2][64];

    const int b = blockIdx.y;
    const int i0 = blockIdx.x * 128;
    const int t = threadIdx.x;
    const int w = t >> 5;
    const int lane = t & 31;
    const int r0 = lane >> 2;
    const int c0 = lane & 3;

    const int irow0 = i0 + w * 16 + r0;
    const int irow1 = irow0 + 8;

    const float4 abt0 = g_ABT[b * N_ + irow0];
    const float4 abt1 = g_ABT[b * N_ + irow1];
    const float A0 = abt0.x, Bc0 = abt0.y, TE0 = abt0.z;
    const float A1 = abt1.x, Bc1 = abt1.y, TE1 = abt1.z;
    float l0 = 0.f, l1 = 0.f;

    float D[8][4];
#pragma unroll
    for (int nb = 0; nb < 8; nb++)
#pragma unroll
        for (int q = 0; q < 4; q++) D[nb][q] = 0.f;

    const uint32_t* mk0 = g_mask + (size_t)irow0 * 32;
    const uint32_t* mk1 = g_mask + (size_t)irow1 * 32;

    auto stage = [&](int jt) {
        const int buf = jt & 1;
#pragma unroll
        for (int q = 0; q < 4; q++) {
            const int cid = q * 256 + t;       // 1024 chunks of 16B
            const int c = cid >> 4;
            const int part = cid & 15;
            cp_async16(smem_u32(&pk[buf][c * PKS + part * 2]),
                       &g_hpk[((size_t)b * 64 + c) * 512 + jt * 32 + part * 2]);
        }
        if (t < 32)
            cp_async16(smem_u32(&ef[buf][t * 2]), &g_EF[b * N_ + jt * 64 + t * 2]);
    };

    stage(0); CP_COMMIT();
    stage(1); CP_COMMIT();

    uint32_t mw00 = __ldg(mk0 + 0), mw01 = __ldg(mk0 + 1);
    uint32_t mw10 = __ldg(mk1 + 0), mw11 = __ldg(mk1 + 1);

    for (int jt = 0; jt < 16; jt++) {
        CP_WAIT1();
        __syncthreads();

        const int jw = (jt < 15) ? (jt + 1) * 2 : 0;
        const uint32_t nw00 = __ldg(mk0 + jw), nw01 = __ldg(mk0 + jw + 1);
        const uint32_t nw10 = __ldg(mk1 + jw), nw11 = __ldg(mk1 + jw + 1);

        const int buf = jt & 1;
        const float2* efp = ef[buf];
        const uint2* pkp = pk[buf];

#pragma unroll
        for (int ks = 0; ks < 4; ks++) {
            // j (within tile) = ks*16 + {2c0, 2c0+1, 2c0+8, 2c0+9}
            const float2 e0 = efp[ks * 16 + 2 * c0];
            const float2 e1 = efp[ks * 16 + 2 * c0 + 1];
            const float2 e2 = efp[ks * 16 + 2 * c0 + 8];
            const float2 e3 = efp[ks * 16 + 2 * c0 + 9];
            const uint32_t w0 = (ks < 2) ? mw00 : mw01;
            const uint32_t w1 = (ks < 2) ? mw10 : mw11;
            const int bb = ((ks & 1) << 4) + 2 * c0;  // bit base within word

            const float p00 = ((w0 >> bb) & 1u)       ? (e0.x >= TE0 ? A0 * e0.x : Bc0 * e0.y) : 0.f;
            const float p01 = ((w0 >> (bb + 1)) & 1u) ? (e1.x >= TE0 ? A0 * e1.x : Bc0 * e1.y) : 0.f;
            const float p02 = ((w0 >> (bb + 8)) & 1u) ? (e2.x >= TE0 ? A0 * e2.x : Bc0 * e2.y) : 0.f;
            const float p03 = ((w0 >> (bb + 9)) & 1u) ? (e3.x >= TE0 ? A0 * e3.x : Bc0 * e3.y) : 0.f;
            const float p10 = ((w1 >> bb) & 1u)       ? (e0.x >= TE1 ? A1 * e0.x : Bc1 * e0.y) : 0.f;
            const float p11 = ((w1 >> (bb + 1)) & 1u) ? (e1.x >= TE1 ? A1 * e1.x : Bc1 * e1.y) : 0.f;
            const float p12 = ((w1 >> (bb + 8)) & 1u) ? (e2.x >= TE1 ? A1 * e2.x : Bc1 * e2.y) : 0.f;
            const float p13 = ((w1 >> (bb + 9)) & 1u) ? (e3.x >= TE1 ? A1 * e3.x : Bc1 * e3.y) : 0.f;

            l0 += p00 + p01 + p02 + p03;
            l1 += p10 + p11 + p12 + p13;

            // A fragments: hi (rounded) + residual
            const __half2 ah0 = __floats2half2_rn(p00, p01);
            const __half2 ah1 = __floats2half2_rn(p10, p11);
            const __half2 ah2 = __floats2half2_rn(p02, p03);
            const __half2 ah3 = __floats2half2_rn(p12, p13);
            const float2 f0 = __half22float2(ah0);
            const float2 f1 = __half22float2(ah1);
            const float2 f2 = __half22float2(ah2);
            const float2 f3 = __half22float2(ah3);
            const __half2 al0 = __floats2half2_rn(p00 - f0.x, p01 - f0.y);
            const __half2 al1 = __floats2half2_rn(p10 - f1.x, p11 - f1.y);
            const __half2 al2 = __floats2half2_rn(p02 - f2.x, p03 - f2.y);
            const __half2 al3 = __floats2half2_rn(p12 - f3.x, p13 - f3.y);
            const uint32_t uh0 = h2u(ah0), uh1 = h2u(ah1), uh2 = h2u(ah2), uh3 = h2u(ah3);
            const uint32_t ul0 = h2u(al0), ul1 = h2u(al1), ul2 = h2u(al2), ul3 = h2u(al3);

#pragma unroll
            for (int nb = 0; nb < 8; nb++) {
                const int crow = nb * 8 + r0;
                const uint2 bv0 = pkp[crow * PKS + ks * 8 + c0];       // (hh2, hl2) b0
                const uint2 bv1 = pkp[crow * PKS + ks * 8 + c0 + 4];   // (hh2, hl2) b1
                mma_f16(D[nb], uh0, uh1, uh2, uh3, bv0.x, bv1.x);      // ph * hh
                mma_f16(D[nb], uh0, uh1, uh2, uh3, bv0.y, bv1.y);      // ph * hl
                mma_f16(D[nb], ul0, ul1, ul2, ul3, bv0.x, bv1.x);      // pl * hh
            }
        }

        __syncthreads();
        if (jt + 2 < 16) stage(jt + 2);
        CP_COMMIT();

        mw00 = nw00; mw01 = nw01; mw10 = nw10; mw11 = nw11;
    }

    // reduce softmax denominators across the quad owning each row
    l0 += __shfl_xor_sync(0xffffffffu, l0, 1);
    l0 += __shfl_xor_sync(0xffffffffu, l0, 2);
    l1 += __shfl_xor_sync(0xffffffffu, l1, 1);
    l1 += __shfl_xor_sync(0xffffffffu, l1, 2);
    const float inv0 = 1.0f / l0;
    const float inv1 = 1.0f / l1;

    float2* o0 = (float2*)(out + ((size_t)b * N_ + irow0) * C_ + 2 * c0);
    float2* o1 = (float2*)(out + ((size_t)b * N_ + irow1) * C_ + 2 * c0);
#pragma unroll
    for (int nb = 0; nb < 8; nb++) {
        float v0 = D[nb][0] * inv0;
        float v1 = D[nb][1] * inv0;
        float v2 = D[nb][2] * inv1;
        float v3 = D[nb][3] * inv1;
        v0 = v0 > 0.f ? v0 : (__expf(v0) - 1.0f);
        v1 = v1 > 0.f ? v1 : (__expf(v1) - 1.0f);
        v2 = v2 > 0.f ? v2 : (__expf(v2) - 1.0f);
        v3 = v3 > 0.f ? v3 : (__expf(v3) - 1.0f);
        o0[nb * 4] = make_float2(v0, v1);
        o1[nb * 4] = make_float2(v2, v3);
    }
}

// ---------------------------------------------------------------------------
extern "C" void kernel_launch(void* const* d_in, const int* in_sizes, int n_in,
                              void* d_out, int out_size) {
    const float* input = (const float*)d_in[0];  // (32,1024,64)
    const float* adj   = (const float*)d_in[1];  // (1024,1024)
    const float* W     = (const float*)d_in[2];  // (64,64)
    const float* a     = (const float*)d_in[3];  // (128,1)
    float* out = (float*)d_out;

    mask_kernel<<<N_ * N_ / (128 * 8), 256>>>(adj);
    gemm_h_kernel<<<BN / 64, 256>>>(input, W);
    dots_kernel<<<BN / 8, 256>>>(a);
    prep_kernel<<<B_, 256>>>();
    attn_kernel<<<dim3(N_ / 128, B_), 256>>>(out);
}

// round 9
// speedup vs baseline: 2.7651x; 1.1134x over previous
#include <cuda_runtime.h>
#include <cuda_fp16.h>
#include <cstdint>
#include <math.h>

#define B_ 32
#define N_ 1024
#define C_ 64
#define BN (B_ * N_)

// device-global scratch (allocation-free rule)
__device__ uint2    g_hpk[B_ * C_ * (N_ / 2)]; // [b][c][npair]: (hh2, hl2) fp16 pairs
__device__ float    g_ssrc[BN];
__device__ float    g_sdst[BN];
__device__ unsigned g_smaxu[B_];               // encoded per-batch max of sdst
__device__ float4   g_ABT[BN];                 // (A, B, TE, -) per row
__device__ float2   g_EF[BN];                  // (E, F) per col
__device__ uint32_t g_mask[N_ * N_ / 32];      // adj>0.5 bitmask

__device__ __forceinline__ uint32_t smem_u32(const void* p) {
    uint32_t a;
    asm("{ .reg .u64 t; cvta.to.shared.u64 t, %1; cvt.u32.u64 %0, t; }" : "=r"(a) : "l"(p));
    return a;
}
__device__ __forceinline__ void cp_async16(uint32_t dst, const void* src) {
    asm volatile("cp.async.cg.shared.global [%0], [%1], 16;" :: "r"(dst), "l"(src));
}
#define CP_COMMIT() asm volatile("cp.async.commit_group;" ::: "memory")
#define CP_WAIT2()  asm volatile("cp.async.wait_group 2;" ::: "memory")

__device__ __forceinline__ void mma_f16(float* d,
                                        uint32_t a0, uint32_t a1, uint32_t a2, uint32_t a3,
                                        uint32_t b0, uint32_t b1) {
    asm volatile(
        "mma.sync.aligned.m16n8k16.row.col.f32.f16.f16.f32 "
        "{%0,%1,%2,%3},{%4,%5,%6,%7},{%8,%9},{%0,%1,%2,%3};"
        : "+f"(d[0]), "+f"(d[1]), "+f"(d[2]), "+f"(d[3])
        : "r"(a0), "r"(a1), "r"(a2), "r"(a3), "r"(b0), "r"(b1));
}
__device__ __forceinline__ uint32_t h2u(__half2 h) { return *(uint32_t*)&h; }

// monotone float<->uint encoding for atomicMax
__device__ __forceinline__ unsigned enc_f(float f) {
    unsigned u = __float_as_uint(f);
    return (u & 0x80000000u) ? ~u : (u | 0x80000000u);
}
__device__ __forceinline__ float dec_f(unsigned u) {
    return (u & 0x80000000u) ? __uint_as_float(u ^ 0x80000000u) : __uint_as_float(~u);
}

// ---------------------------------------------------------------------------
// Kernel M: adj > 0.5 bitmask via warp ballot
// ---------------------------------------------------------------------------
__global__ void __launch_bounds__(256) mask_kernel(const float* __restrict__ adj) {
    const int gw = (blockIdx.x * 256 + threadIdx.x) >> 5;  // 0..8191
    const int lane = threadIdx.x & 31;
    const float* base = adj + (size_t)gw * 128;
#pragma unroll
    for (int q = 0; q < 4; q++) {
        float v = __ldg(base + q * 32 + lane);
        uint32_t m = __ballot_sync(0xffffffffu, v > 0.5f);
        if (lane == 0) g_mask[gw * 4 + q] = m;
    }
}

// ---------------------------------------------------------------------------
// Kernel A: h = input @ W fused with dots (ssrc/sdst) + per-batch sdst max.
// 4x4 register tile; writes only the packed fp16 hi/lo array g_hpk.
// ---------------------------------------------------------------------------
__global__ void __launch_bounds__(256) gemm_h_kernel(const float* __restrict__ in,
                                                     const float* __restrict__ W,
                                                     const float* __restrict__ av) {
    __shared__ float Ws[64 * 64];
    __shared__ float Is[64 * 64];
    __shared__ float red[8];
    const int t = threadIdx.x;
    const int row0 = blockIdx.x * 64;

    const float4* W4 = (const float4*)W;
    float4* Ws4 = (float4*)Ws;
#pragma unroll
    for (int q = 0; q < 4; q++) Ws4[t + q * 256] = W4[t + q * 256];
    const float4* in4 = (const float4*)(in + row0 * 64);
    float4* Is4 = (float4*)Is;
#pragma unroll
    for (int q = 0; q < 4; q++) Is4[t + q * 256] = in4[t + q * 256];
    __syncthreads();

    const int tx = t & 15;
    const int ty = t >> 4;
    float acc[4][4];
#pragma unroll
    for (int i = 0; i < 4; i++)
#pragma unroll
        for (int j = 0; j < 4; j++) acc[i][j] = 0.f;

#pragma unroll
    for (int k = 0; k < 64; k++) {
        const float4 b = *(const float4*)&Ws[k * 64 + 4 * tx];
        const float a0 = Is[(4 * ty + 0) * 64 + k];
        const float a1 = Is[(4 * ty + 1) * 64 + k];
        const float a2 = Is[(4 * ty + 2) * 64 + k];
        const float a3 = Is[(4 * ty + 3) * 64 + k];
        acc[0][0] = fmaf(a0, b.x, acc[0][0]); acc[0][1] = fmaf(a0, b.y, acc[0][1]);
        acc[0][2] = fmaf(a0, b.z, acc[0][2]); acc[0][3] = fmaf(a0, b.w, acc[0][3]);
        acc[1][0] = fmaf(a1, b.x, acc[1][0]); acc[1][1] = fmaf(a1, b.y, acc[1][1]);
        acc[1][2] = fmaf(a1, b.z, acc[1][2]); acc[1][3] = fmaf(a1, b.w, acc[1][3]);
        acc[2][0] = fmaf(a2, b.x, acc[2][0]); acc[2][1] = fmaf(a2, b.y, acc[2][1]);
        acc[2][2] = fmaf(a2, b.z, acc[2][2]); acc[2][3] = fmaf(a2, b.w, acc[2][3]);
        acc[3][0] = fmaf(a3, b.x, acc[3][0]); acc[3][1] = fmaf(a3, b.y, acc[3][1]);
        acc[3][2] = fmaf(a3, b.z, acc[3][2]); acc[3][3] = fmaf(a3, b.w, acc[3][3]);
    }

    const int b = row0 >> 10;
    const int n0 = row0 & 1023;

    // packed fp16 hi/lo pairs along n
#pragma unroll
    for (int p = 0; p < 2; p++) {
        const int npair = (n0 + 4 * ty) / 2 + p;
#pragma unroll
        for (int j = 0; j < 4; j++) {
            const float va = acc[2 * p + 0][j];
            const float vb = acc[2 * p + 1][j];
            const __half ha = __float2half_rn(va);
            const __half hb = __float2half_rn(vb);
            uint2 pkv;
            pkv.x = h2u(__halves2half2(ha, hb));
            pkv.y = h2u(__floats2half2_rn(va - __half2float(ha), vb - __half2float(hb)));
            g_hpk[((size_t)b * 64 + 4 * tx + j) * 512 + npair] = pkv;
        }
    }

    // fused dots: ssrc/sdst for rows 4ty+i, reduce over tx (16 lanes, xor<=8)
    float as_[4], ad_[4];
#pragma unroll
    for (int j = 0; j < 4; j++) {
        as_[j] = __ldg(av + 4 * tx + j);
        ad_[j] = __ldg(av + 64 + 4 * tx + j);
    }
    float sdmax = -INFINITY;
#pragma unroll
    for (int i = 0; i < 4; i++) {
        float ss = acc[i][0] * as_[0] + acc[i][1] * as_[1] + acc[i][2] * as_[2] + acc[i][3] * as_[3];
        float sd = acc[i][0] * ad_[0] + acc[i][1] * ad_[1] + acc[i][2] * ad_[2] + acc[i][3] * ad_[3];
#pragma unroll
        for (int o = 8; o; o >>= 1) {
            ss += __shfl_xor_sync(0xffffffffu, ss, o);
            sd += __shfl_xor_sync(0xffffffffu, sd, o);
        }
        if (tx == 0) {
            const int row = row0 + 4 * ty + i;
            g_ssrc[row] = ss;
            g_sdst[row] = sd;
        }
        sdmax = fmaxf(sdmax, sd);
    }
    // block max -> one atomic per block
#pragma unroll
    for (int o = 16; o; o >>= 1) sdmax = fmaxf(sdmax, __shfl_xor_sync(0xffffffffu, sdmax, o));
    if ((t & 31) == 0) red[t >> 5] = sdmax;
    __syncthreads();
    if (t == 0) {
        float m = red[0];
#pragma unroll
        for (int i = 1; i < 8; i++) m = fmaxf(m, red[i]);
        atomicMax(&g_smaxu[b], enc_f(m));
    }
}

// ---------------------------------------------------------------------------
// Kernel C: factored-softmax coefficients (elementwise, one row per thread)
// ---------------------------------------------------------------------------
__global__ void __launch_bounds__(256) prep_kernel() {
    const int idx = blockIdx.x * 256 + threadIdx.x;  // 0..32767
    const int b = idx >> 10;
    const float S = dec_f(g_smaxu[b]);
    const float ss = g_ssrc[idx];
    const float sd = g_sdst[idx];
    float mm = ss + S; mm = mm >= 0.f ? mm : 0.2f * mm;
    g_ABT[idx] = make_float4(__expf(ss - mm), __expf(0.2f * ss - mm), __expf(-ss), 0.f);
    g_EF[idx] = make_float2(__expf(sd), __expf(0.2f * sd));
}

// ---------------------------------------------------------------------------
// Kernel D: fused attention. Factored exp, bitmask gates, 4-deep cp.async
// pipeline (one __syncthreads per tile), PV via 3xFP16 mma m16n8k16.
// ---------------------------------------------------------------------------
#define PKS 36  // uint2 stride per c-row
#define PKBUF_ELEMS (64 * PKS)
#define SMEM_DYN (4 * PKBUF_ELEMS * 8 + 4 * 64 * 8)

__global__ void __launch_bounds__(256, 2) attn_kernel(float* __restrict__ out) {
    extern __shared__ char sm[];
    uint2* pkbase = (uint2*)sm;
    float2* efbase = (float2*)(sm + 4 * PKBUF_ELEMS * 8);

    const int b = blockIdx.y;
    const int i0 = blockIdx.x * 128;
    const int t = threadIdx.x;
    const int w = t >> 5;
    const int lane = t & 31;
    const int r0 = lane >> 2;
    const int c0 = lane & 3;

    const int irow0 = i0 + w * 16 + r0;
    const int irow1 = irow0 + 8;

    const float4 abt0 = g_ABT[b * N_ + irow0];
    const float4 abt1 = g_ABT[b * N_ + irow1];
    const float A0 = abt0.x, Bc0 = abt0.y, TE0 = abt0.z;
    const float A1 = abt1.x, Bc1 = abt1.y, TE1 = abt1.z;
    float l0 = 0.f, l1 = 0.f;

    float D[8][4];
#pragma unroll
    for (int nb = 0; nb < 8; nb++)
#pragma unroll
        for (int q = 0; q < 4; q++) D[nb][q] = 0.f;

    const uint32_t* mk0 = g_mask + (size_t)irow0 * 32;
    const uint32_t* mk1 = g_mask + (size_t)irow1 * 32;

    auto stage = [&](int jt) {
        const int buf = jt & 3;
        uint2* pkd = pkbase + buf * PKBUF_ELEMS;
#pragma unroll
        for (int q = 0; q < 4; q++) {
            const int cid = q * 256 + t;       // 1024 chunks of 16B
            const int c = cid >> 4;
            const int part = cid & 15;
            cp_async16(smem_u32(&pkd[c * PKS + part * 2]),
                       &g_hpk[((size_t)b * 64 + c) * 512 + jt * 32 + part * 2]);
        }
        if (t < 32)
            cp_async16(smem_u32(&efbase[buf * 64 + t * 2]), &g_EF[b * N_ + jt * 64 + t * 2]);
    };

    stage(0); CP_COMMIT();
    stage(1); CP_COMMIT();
    stage(2); CP_COMMIT();

    uint32_t mw00 = __ldg(mk0 + 0), mw01 = __ldg(mk0 + 1);
    uint32_t mw10 = __ldg(mk1 + 0), mw11 = __ldg(mk1 + 1);

    for (int jt = 0; jt < 16; jt++) {
        CP_WAIT2();
        __syncthreads();

        const int jw = (jt < 15) ? (jt + 1) * 2 : 0;
        const uint32_t nw00 = __ldg(mk0 + jw), nw01 = __ldg(mk0 + jw + 1);
        const uint32_t nw10 = __ldg(mk1 + jw), nw11 = __ldg(mk1 + jw + 1);

        const int buf = jt & 3;
        const float2* efp = efbase + buf * 64;
        const uint2* pkp = pkbase + buf * PKBUF_ELEMS;

#pragma unroll
        for (int ks = 0; ks < 4; ks++) {
            const float2 e0 = efp[ks * 16 + 2 * c0];
            const float2 e1 = efp[ks * 16 + 2 * c0 + 1];
            const float2 e2 = efp[ks * 16 + 2 * c0 + 8];
            const float2 e3 = efp[ks * 16 + 2 * c0 + 9];
            const uint32_t w0 = (ks < 2) ? mw00 : mw01;
            const uint32_t w1 = (ks < 2) ? mw10 : mw11;
            const int bb = ((ks & 1) << 4) + 2 * c0;

            const float p00 = ((w0 >> bb) & 1u)       ? (e0.x >= TE0 ? A0 * e0.x : Bc0 * e0.y) : 0.f;
            const float p01 = ((w0 >> (bb + 1)) & 1u) ? (e1.x >= TE0 ? A0 * e1.x : Bc0 * e1.y) : 0.f;
            const float p02 = ((w0 >> (bb + 8)) & 1u) ? (e2.x >= TE0 ? A0 * e2.x : Bc0 * e2.y) : 0.f;
            const float p03 = ((w0 >> (bb + 9)) & 1u) ? (e3.x >= TE0 ? A0 * e3.x : Bc0 * e3.y) : 0.f;
            const float p10 = ((w1 >> bb) & 1u)       ? (e0.x >= TE1 ? A1 * e0.x : Bc1 * e0.y) : 0.f;
            const float p11 = ((w1 >> (bb + 1)) & 1u) ? (e1.x >= TE1 ? A1 * e1.x : Bc1 * e1.y) : 0.f;
            const float p12 = ((w1 >> (bb + 8)) & 1u) ? (e2.x >= TE1 ? A1 * e2.x : Bc1 * e2.y) : 0.f;
            const float p13 = ((w1 >> (bb + 9)) & 1u) ? (e3.x >= TE1 ? A1 * e3.x : Bc1 * e3.y) : 0.f;

            l0 += p00 + p01 + p02 + p03;
            l1 += p10 + p11 + p12 + p13;

            const __half2 ah0 = __floats2half2_rn(p00, p01);
            const __half2 ah1 = __floats2half2_rn(p10, p11);
            const __half2 ah2 = __floats2half2_rn(p02, p03);
            const __half2 ah3 = __floats2half2_rn(p12, p13);
            const float2 f0 = __half22float2(ah0);
            const float2 f1 = __half22float2(ah1);
            const float2 f2 = __half22float2(ah2);
            const float2 f3 = __half22float2(ah3);
            const __half2 al0 = __floats2half2_rn(p00 - f0.x, p01 - f0.y);
            const __half2 al1 = __floats2half2_rn(p10 - f1.x, p11 - f1.y);
            const __half2 al2 = __floats2half2_rn(p02 - f2.x, p03 - f2.y);
            const __half2 al3 = __floats2half2_rn(p12 - f3.x, p13 - f3.y);
            const uint32_t uh0 = h2u(ah0), uh1 = h2u(ah1), uh2 = h2u(ah2), uh3 = h2u(ah3);
            const uint32_t ul0 = h2u(al0), ul1 = h2u(al1), ul2 = h2u(al2), ul3 = h2u(al3);

#pragma unroll
            for (int nb = 0; nb < 8; nb++) {
                const int crow = nb * 8 + r0;
                const uint2 bv0 = pkp[crow * PKS + ks * 8 + c0];
                const uint2 bv1 = pkp[crow * PKS + ks * 8 + c0 + 4];
                mma_f16(D[nb], uh0, uh1, uh2, uh3, bv0.x, bv1.x);  // ph * hh
                mma_f16(D[nb], uh0, uh1, uh2, uh3, bv0.y, bv1.y);  // ph * hl
                mma_f16(D[nb], ul0, ul1, ul2, ul3, bv0.x, bv1.x);  // pl * hh
            }
        }

        if (jt + 3 < 16) stage(jt + 3);
        CP_COMMIT();

        mw00 = nw00; mw01 = nw01; mw10 = nw10; mw11 = nw11;
    }

    l0 += __shfl_xor_sync(0xffffffffu, l0, 1);
    l0 += __shfl_xor_sync(0xffffffffu, l0, 2);
    l1 += __shfl_xor_sync(0xffffffffu, l1, 1);
    l1 += __shfl_xor_sync(0xffffffffu, l1, 2);
    const float inv0 = 1.0f / l0;
    const float inv1 = 1.0f / l1;

    float2* o0 = (float2*)(out + ((size_t)b * N_ + irow0) * C_ + 2 * c0);
    float2* o1 = (float2*)(out + ((size_t)b * N_ + irow1) * C_ + 2 * c0);
#pragma unroll
    for (int nb = 0; nb < 8; nb++) {
        float v0 = D[nb][0] * inv0;
        float v1 = D[nb][1] * inv0;
        float v2 = D[nb][2] * inv1;
        float v3 = D[nb][3] * inv1;
        v0 = v0 > 0.f ? v0 : (__expf(v0) - 1.0f);
        v1 = v1 > 0.f ? v1 : (__expf(v1) - 1.0f);
        v2 = v2 > 0.f ? v2 : (__expf(v2) - 1.0f);
        v3 = v3 > 0.f ? v3 : (__expf(v3) - 1.0f);
        o0[nb * 4] = make_float2(v0, v1);
        o1[nb * 4] = make_float2(v2, v3);
    }
}

// ---------------------------------------------------------------------------
extern "C" void kernel_launch(void* const* d_in, const int* in_sizes, int n_in,
                              void* d_out, int out_size) {
    const float* input = (const float*)d_in[0];  // (32,1024,64)
    const float* adj   = (const float*)d_in[1];  // (1024,1024)
    const float* W     = (const float*)d_in[2];  // (64,64)
    const float* a     = (const float*)d_in[3];  // (128,1)
    float* out = (float*)d_out;

    cudaFuncSetAttribute(attn_kernel, cudaFuncAttributeMaxDynamicSharedMemorySize, SMEM_DYN);

    mask_kernel<<<N_ * N_ / (128 * 8), 256>>>(adj);
    gemm_h_kernel<<<BN / 64, 256>>>(input, W, a);
    prep_kernel<<<BN / 256, 256>>>();
    attn_kernel<<<dim3(N_ / 128, B_), 256, SMEM_DYN>>>(out);
}

// round 10
// speedup vs baseline: 2.9279x; 1.0589x over previous
#include <cuda_runtime.h>
#include <cuda_fp16.h>
#include <cstdint>
#include <math.h>

#define B_ 32
#define N_ 1024
#define C_ 64
#define BN (B_ * N_)

typedef unsigned long long ULL;

// device-global scratch (allocation-free rule)
__device__ uint2    g_hpk[B_ * C_ * (N_ / 2)]; // [b][c][npair]: (hh2, hl2) fp16 pairs
__device__ float    g_ssrc[BN];
__device__ float    g_sdst[BN];
__device__ unsigned g_smaxu[B_];               // encoded per-batch max of sdst
__device__ float2   g_AB[BN];                  // (A, B) per row
__device__ float2   g_EF[BN];                  // (E, F) per col
__device__ uint32_t g_mask[N_ * N_ / 32];      // adj>0.5 bitmask

__device__ __forceinline__ uint32_t smem_u32(const void* p) {
    uint32_t a;
    asm("{ .reg .u64 t; cvta.to.shared.u64 t, %1; cvt.u32.u64 %0, t; }" : "=r"(a) : "l"(p));
    return a;
}
__device__ __forceinline__ void cp_async16(uint32_t dst, const void* src) {
    asm volatile("cp.async.cg.shared.global [%0], [%1], 16;" :: "r"(dst), "l"(src));
}
#define CP_COMMIT() asm volatile("cp.async.commit_group;" ::: "memory")
#define CP_WAIT2()  asm volatile("cp.async.wait_group 2;" ::: "memory")

__device__ __forceinline__ void mma_f16(float* d,
                                        uint32_t a0, uint32_t a1, uint32_t a2, uint32_t a3,
                                        uint32_t b0, uint32_t b1) {
    asm volatile(
        "mma.sync.aligned.m16n8k16.row.col.f32.f16.f16.f32 "
        "{%0,%1,%2,%3},{%4,%5,%6,%7},{%8,%9},{%0,%1,%2,%3};"
        : "+f"(d[0]), "+f"(d[1]), "+f"(d[2]), "+f"(d[3])
        : "r"(a0), "r"(a1), "r"(a2), "r"(a3), "r"(b0), "r"(b1));
}
__device__ __forceinline__ uint32_t h2u(__half2 h) { return *(uint32_t*)&h; }

// packed fp32x2: q = ab * ef (one instruction, two products)
__device__ __forceinline__ float2 mul2f(ULL ab, ULL ef) {
    ULL q;
    asm("mul.rn.f32x2 %0, %1, %2;" : "=l"(q) : "l"(ab), "l"(ef));
    float2 r;
    asm("mov.b64 {%0,%1}, %2;" : "=f"(r.x), "=f"(r.y) : "l"(q));
    return r;
}
__device__ __forceinline__ ULL pack2f(float x, float y) {
    ULL v; asm("mov.b64 %0, {%1,%2};" : "=l"(v) : "f"(x), "f"(y)); return v;
}
__device__ __forceinline__ ULL ld_s64(uint32_t addr) {
    ULL v; asm volatile("ld.shared.b64 %0, [%1];" : "=l"(v) : "r"(addr)); return v;
}

// monotone float<->uint encoding for atomicMax
__device__ __forceinline__ unsigned enc_f(float f) {
    unsigned u = __float_as_uint(f);
    return (u & 0x80000000u) ? ~u : (u | 0x80000000u);
}
__device__ __forceinline__ float dec_f(unsigned u) {
    return (u & 0x80000000u) ? __uint_as_float(u ^ 0x80000000u) : __uint_as_float(~u);
}

// ---------------------------------------------------------------------------
// Kernel M: adj > 0.5 bitmask via warp ballot
// ---------------------------------------------------------------------------
__global__ void __launch_bounds__(256) mask_kernel(const float* __restrict__ adj) {
    const int gw = (blockIdx.x * 256 + threadIdx.x) >> 5;  // 0..8191
    const int lane = threadIdx.x & 31;
    const float* base = adj + (size_t)gw * 128;
#pragma unroll
    for (int q = 0; q < 4; q++) {
        float v = __ldg(base + q * 32 + lane);
        uint32_t m = __ballot_sync(0xffffffffu, v > 0.5f);
        if (lane == 0) g_mask[gw * 4 + q] = m;
    }
}

// ---------------------------------------------------------------------------
// Kernel A: h = input @ W fused with dots (ssrc/sdst) + per-batch sdst max.
// ---------------------------------------------------------------------------
__global__ void __launch_bounds__(256) gemm_h_kernel(const float* __restrict__ in,
                                                     const float* __restrict__ W,
                                                     const float* __restrict__ av) {
    __shared__ float Ws[64 * 64];
    __shared__ float Is[64 * 64];
    __shared__ float red[8];
    const int t = threadIdx.x;
    const int row0 = blockIdx.x * 64;

    const float4* W4 = (const float4*)W;
    float4* Ws4 = (float4*)Ws;
#pragma unroll
    for (int q = 0; q < 4; q++) Ws4[t + q * 256] = W4[t + q * 256];
    const float4* in4 = (const float4*)(in + row0 * 64);
    float4* Is4 = (float4*)Is;
#pragma unroll
    for (int q = 0; q < 4; q++) Is4[t + q * 256] = in4[t + q * 256];
    __syncthreads();

    const int tx = t & 15;
    const int ty = t >> 4;
    float acc[4][4];
#pragma unroll
    for (int i = 0; i < 4; i++)
#pragma unroll
        for (int j = 0; j < 4; j++) acc[i][j] = 0.f;

#pragma unroll
    for (int k = 0; k < 64; k++) {
        const float4 b = *(const float4*)&Ws[k * 64 + 4 * tx];
        const float a0 = Is[(4 * ty + 0) * 64 + k];
        const float a1 = Is[(4 * ty + 1) * 64 + k];
        const float a2 = Is[(4 * ty + 2) * 64 + k];
        const float a3 = Is[(4 * ty + 3) * 64 + k];
        acc[0][0] = fmaf(a0, b.x, acc[0][0]); acc[0][1] = fmaf(a0, b.y, acc[0][1]);
        acc[0][2] = fmaf(a0, b.z, acc[0][2]); acc[0][3] = fmaf(a0, b.w, acc[0][3]);
        acc[1][0] = fmaf(a1, b.x, acc[1][0]); acc[1][1] = fmaf(a1, b.y, acc[1][1]);
        acc[1][2] = fmaf(a1, b.z, acc[1][2]); acc[1][3] = fmaf(a1, b.w, acc[1][3]);
        acc[2][0] = fmaf(a2, b.x, acc[2][0]); acc[2][1] = fmaf(a2, b.y, acc[2][1]);
        acc[2][2] = fmaf(a2, b.z, acc[2][2]); acc[2][3] = fmaf(a2, b.w, acc[2][3]);
        acc[3][0] = fmaf(a3, b.x, acc[3][0]); acc[3][1] = fmaf(a3, b.y, acc[3][1]);
        acc[3][2] = fmaf(a3, b.z, acc[3][2]); acc[3][3] = fmaf(a3, b.w, acc[3][3]);
    }

    const int b = row0 >> 10;
    const int n0 = row0 & 1023;

#pragma unroll
    for (int p = 0; p < 2; p++) {
        const int npair = (n0 + 4 * ty) / 2 + p;
#pragma unroll
        for (int j = 0; j < 4; j++) {
            const float va = acc[2 * p + 0][j];
            const float vb = acc[2 * p + 1][j];
            const __half ha = __float2half_rn(va);
            const __half hb = __float2half_rn(vb);
            uint2 pkv;
            pkv.x = h2u(__halves2half2(ha, hb));
            pkv.y = h2u(__floats2half2_rn(va - __half2float(ha), vb - __half2float(hb)));
            g_hpk[((size_t)b * 64 + 4 * tx + j) * 512 + npair] = pkv;
        }
    }

    float as_[4], ad_[4];
#pragma unroll
    for (int j = 0; j < 4; j++) {
        as_[j] = __ldg(av + 4 * tx + j);
        ad_[j] = __ldg(av + 64 + 4 * tx + j);
    }
    float sdmax = -INFINITY;
#pragma unroll
    for (int i = 0; i < 4; i++) {
        float ss = acc[i][0] * as_[0] + acc[i][1] * as_[1] + acc[i][2] * as_[2] + acc[i][3] * as_[3];
        float sd = acc[i][0] * ad_[0] + acc[i][1] * ad_[1] + acc[i][2] * ad_[2] + acc[i][3] * ad_[3];
#pragma unroll
        for (int o = 8; o; o >>= 1) {
            ss += __shfl_xor_sync(0xffffffffu, ss, o);
            sd += __shfl_xor_sync(0xffffffffu, sd, o);
        }
        if (tx == 0) {
            const int row = row0 + 4 * ty + i;
            g_ssrc[row] = ss;
            g_sdst[row] = sd;
        }
        sdmax = fmaxf(sdmax, sd);
    }
#pragma unroll
    for (int o = 16; o; o >>= 1) sdmax = fmaxf(sdmax, __shfl_xor_sync(0xffffffffu, sdmax, o));
    if ((t & 31) == 0) red[t >> 5] = sdmax;
    __syncthreads();
    if (t == 0) {
        float m = red[0];
#pragma unroll
        for (int i = 1; i < 8; i++) m = fmaxf(m, red[i]);
        atomicMax(&g_smaxu[b], enc_f(m));
    }
}

// ---------------------------------------------------------------------------
// Kernel C: factored-softmax coefficients (elementwise)
//   p_ij = max(A_i*E_j, B_i*F_j) since lrelu(x)=max(x,0.2x), exp monotone
// ---------------------------------------------------------------------------
__global__ void __launch_bounds__(256) prep_kernel() {
    const int idx = blockIdx.x * 256 + threadIdx.x;
    const int b = idx >> 10;
    const float S = dec_f(g_smaxu[b]);
    const float ss = g_ssrc[idx];
    const float sd = g_sdst[idx];
    float mm = ss + S; mm = mm >= 0.f ? mm : 0.2f * mm;
    g_AB[idx] = make_float2(__expf(ss - mm), __expf(0.2f * ss - mm));
    g_EF[idx] = make_float2(__expf(sd), __expf(0.2f * sd));
}

// ---------------------------------------------------------------------------
// Kernel D: fused attention. p = max(AE, BF) via f32x2; bitmask gates with
// hoisted shifts; l via ones-column MMA; 4-deep cp.async; 3xFP16 m16n8k16.
// ---------------------------------------------------------------------------
#define PKS 36
#define PKBUF_ELEMS (64 * PKS)
#define SMEM_DYN (4 * PKBUF_ELEMS * 8 + 4 * 64 * 8)
#define ONES2 0x3C003C00u

__global__ void __launch_bounds__(256, 2) attn_kernel(float* __restrict__ out) {
    extern __shared__ char sm[];
    uint2* pkbase = (uint2*)sm;
    float2* efbase = (float2*)(sm + 4 * PKBUF_ELEMS * 8);
    const uint32_t ef_addr0 = smem_u32(efbase);

    const int b = blockIdx.y;
    const int i0 = blockIdx.x * 128;
    const int t = threadIdx.x;
    const int w = t >> 5;
    const int lane = t & 31;
    const int r0 = lane >> 2;
    const int c0 = lane & 3;

    const int irow0 = i0 + w * 16 + r0;
    const int irow1 = irow0 + 8;

    const float2 ab0 = g_AB[b * N_ + irow0];
    const float2 ab1 = g_AB[b * N_ + irow1];
    const ULL AB0 = pack2f(ab0.x, ab0.y);
    const ULL AB1 = pack2f(ab1.x, ab1.y);

    float D[8][4];
#pragma unroll
    for (int nb = 0; nb < 8; nb++)
#pragma unroll
        for (int q = 0; q < 4; q++) D[nb][q] = 0.f;
    float Dl[4] = {0.f, 0.f, 0.f, 0.f};

    const uint32_t* mk0 = g_mask + (size_t)irow0 * 32;
    const uint32_t* mk1 = g_mask + (size_t)irow1 * 32;

    auto stage = [&](int jt) {
        const int buf = jt & 3;
        uint2* pkd = pkbase + buf * PKBUF_ELEMS;
#pragma unroll
        for (int q = 0; q < 4; q++) {
            const int cid = q * 256 + t;
            const int c = cid >> 4;
            const int part = cid & 15;
            cp_async16(smem_u32(&pkd[c * PKS + part * 2]),
                       &g_hpk[((size_t)b * 64 + c) * 512 + jt * 32 + part * 2]);
        }
        if (t < 32)
            cp_async16(smem_u32(&efbase[buf * 64 + t * 2]), &g_EF[b * N_ + jt * 64 + t * 2]);
    };

    stage(0); CP_COMMIT();
    stage(1); CP_COMMIT();
    stage(2); CP_COMMIT();

    uint32_t mw00 = __ldg(mk0 + 0), mw01 = __ldg(mk0 + 1);
    uint32_t mw10 = __ldg(mk1 + 0), mw11 = __ldg(mk1 + 1);

    for (int jt = 0; jt < 16; jt++) {
        CP_WAIT2();
        __syncthreads();

        const int jw = (jt < 15) ? (jt + 1) * 2 : 0;
        const uint32_t nw00 = __ldg(mk0 + jw), nw01 = __ldg(mk0 + jw + 1);
        const uint32_t nw10 = __ldg(mk1 + jw), nw11 = __ldg(mk1 + jw + 1);

        const int buf = jt & 3;
        const uint2* pkp = pkbase + buf * PKBUF_ELEMS;
        const uint32_t efs = ef_addr0 + buf * 512 + 2 * c0 * 8;

        // hoisted gate-word shifts: bit positions become immediates
        const uint32_t wsh00 = mw00 >> (2 * c0), wsh01 = mw01 >> (2 * c0);
        const uint32_t wsh10 = mw10 >> (2 * c0), wsh11 = mw11 >> (2 * c0);

#pragma unroll
        for (int ks = 0; ks < 4; ks++) {
            const uint32_t ea_addr = efs + ks * 16 * 8;
            const ULL ea = ld_s64(ea_addr);
            const ULL eb = ld_s64(ea_addr + 8);
            const ULL ec = ld_s64(ea_addr + 64);
            const ULL ed = ld_s64(ea_addr + 72);
            const uint32_t ws0 = (ks < 2) ? wsh00 : wsh01;
            const uint32_t ws1 = (ks < 2) ? wsh10 : wsh11;
            const int bo = (ks & 1) << 4;

            float2 q;
            q = mul2f(AB0, ea); float p00 = fmaxf(q.x, q.y);
            q = mul2f(AB0, eb); float p01 = fmaxf(q.x, q.y);
            q = mul2f(AB0, ec); float p02 = fmaxf(q.x, q.y);
            q = mul2f(AB0, ed); float p03 = fmaxf(q.x, q.y);
            q = mul2f(AB1, ea); float p10 = fmaxf(q.x, q.y);
            q = mul2f(AB1, eb); float p11 = fmaxf(q.x, q.y);
            q = mul2f(AB1, ec); float p12 = fmaxf(q.x, q.y);
            q = mul2f(AB1, ed); float p13 = fmaxf(q.x, q.y);

            p00 = ((ws0 >> (bo + 0)) & 1u) ? p00 : 0.f;
            p01 = ((ws0 >> (bo + 1)) & 1u) ? p01 : 0.f;
            p02 = ((ws0 >> (bo + 8)) & 1u) ? p02 : 0.f;
            p03 = ((ws0 >> (bo + 9)) & 1u) ? p03 : 0.f;
            p10 = ((ws1 >> (bo + 0)) & 1u) ? p10 : 0.f;
            p11 = ((ws1 >> (bo + 1)) & 1u) ? p11 : 0.f;
            p12 = ((ws1 >> (bo + 8)) & 1u) ? p12 : 0.f;
            p13 = ((ws1 >> (bo + 9)) & 1u) ? p13 : 0.f;

            const __half2 ah0 = __floats2half2_rn(p00, p01);
            const __half2 ah1 = __floats2half2_rn(p10, p11);
            const __half2 ah2 = __floats2half2_rn(p02, p03);
            const __half2 ah3 = __floats2half2_rn(p12, p13);
            const float2 f0 = __half22float2(ah0);
            const float2 f1 = __half22float2(ah1);
            const float2 f2 = __half22float2(ah2);
            const float2 f3 = __half22float2(ah3);
            const __half2 al0 = __floats2half2_rn(p00 - f0.x, p01 - f0.y);
            const __half2 al1 = __floats2half2_rn(p10 - f1.x, p11 - f1.y);
            const __half2 al2 = __floats2half2_rn(p02 - f2.x, p03 - f2.y);
            const __half2 al3 = __floats2half2_rn(p12 - f3.x, p13 - f3.y);
            const uint32_t uh0 = h2u(ah0), uh1 = h2u(ah1), uh2 = h2u(ah2), uh3 = h2u(ah3);
            const uint32_t ul0 = h2u(al0), ul1 = h2u(al1), ul2 = h2u(al2), ul3 = h2u(al3);

            // l accumulation via ones-column MMA: Dl[0]=l(irow0), Dl[2]=l(irow1)
            mma_f16(Dl, uh0, uh1, uh2, uh3, ONES2, ONES2);
            mma_f16(Dl, ul0, ul1, ul2, ul3, ONES2, ONES2);

#pragma unroll
            for (int nb = 0; nb < 8; nb++) {
                const int crow = nb * 8 + r0;
                const uint2 bv0 = pkp[crow * PKS + ks * 8 + c0];
                const uint2 bv1 = pkp[crow * PKS + ks * 8 + c0 + 4];
                mma_f16(D[nb], uh0, uh1, uh2, uh3, bv0.x, bv1.x);  // ph * hh
                mma_f16(D[nb], uh0, uh1, uh2, uh3, bv0.y, bv1.y);  // ph * hl
                mma_f16(D[nb], ul0, ul1, ul2, ul3, bv0.x, bv1.x);  // pl * hh
            }
        }

        if (jt + 3 < 16) stage(jt + 3);
        CP_COMMIT();

        mw00 = nw00; mw01 = nw01; mw10 = nw10; mw11 = nw11;
    }

    // l comes fully reduced from the ones-column MMA (k-dim spans the quad)
    const float inv0 = 1.0f / Dl[0];
    const float inv1 = 1.0f / Dl[2];

    float2* o0 = (float2*)(out + ((size_t)b * N_ + irow0) * C_ + 2 * c0);
    float2* o1 = (float2*)(out + ((size_t)b * N_ + irow1) * C_ + 2 * c0);
#pragma unroll
    for (int nb = 0; nb < 8; nb++) {
        float v0 = D[nb][0] * inv0;
        float v1 = D[nb][1] * inv0;
        float v2 = D[nb][2] * inv1;
        float v3 = D[nb][3] * inv1;
        v0 = v0 > 0.f ? v0 : (__expf(v0) - 1.0f);
        v1 = v1 > 0.f ? v1 : (__expf(v1) - 1.0f);
        v2 = v2 > 0.f ? v2 : (__expf(v2) - 1.0f);
        v3 = v3 > 0.f ? v3 : (__expf(v3) - 1.0f);
        o0[nb * 4] = make_float2(v0, v1);
        o1[nb * 4] = make_float2(v2, v3);
    }
}

// ---------------------------------------------------------------------------
extern "C" void kernel_launch(void* const* d_in, const int* in_sizes, int n_in,
                              void* d_out, int out_size) {
    const float* input = (const float*)d_in[0];  // (32,1024,64)
    const float* adj   = (const float*)d_in[1];  // (1024,1024)
    const float* W     = (const float*)d_in[2];  // (64,64)
    const float* a     = (const float*)d_in[3];  // (128,1)
    float* out = (float*)d_out;

    cudaFuncSetAttribute(attn_kernel, cudaFuncAttributeMaxDynamicSharedMemorySize, SMEM_DYN);

    mask_kernel<<<N_ * N_ / (128 * 8), 256>>>(adj);
    gemm_h_kernel<<<BN / 64, 256>>>(input, W, a);
    prep_kernel<<<BN / 256, 256>>>();
    attn_kernel<<<dim3(N_ / 128, B_), 256, SMEM_DYN>>>(out);
}

// round 11
// speedup vs baseline: 2.9782x; 1.0172x over previous
#include <cuda_runtime.h>
#include <cuda_fp16.h>
#include <cstdint>
#include <math.h>

#define B_ 32
#define N_ 1024
#define C_ 64
#define BN (B_ * N_)

typedef unsigned long long ULL;

// device-global scratch (allocation-free rule)
__device__ uint2    g_hpk[B_ * C_ * (N_ / 2)]; // [b][c][npair]: (hh2, hl2) fp16 pairs
__device__ float    g_ssrc[BN];
__device__ float    g_sdst[BN];
__device__ unsigned g_smaxu[B_];               // encoded per-batch max of sdst
__device__ float2   g_AB[BN];                  // (A, B) per row
__device__ float2   g_EF[BN];                  // (E, F) per col
__device__ uint32_t g_mask[N_ * N_ / 32];      // adj>0.5 bitmask

__device__ __forceinline__ uint32_t smem_u32(const void* p) {
    uint32_t a;
    asm("{ .reg .u64 t; cvta.to.shared.u64 t, %1; cvt.u32.u64 %0, t; }" : "=r"(a) : "l"(p));
    return a;
}
__device__ __forceinline__ void cp_async16(uint32_t dst, const void* src) {
    asm volatile("cp.async.cg.shared.global [%0], [%1], 16;" :: "r"(dst), "l"(src));
}
#define CP_COMMIT() asm volatile("cp.async.commit_group;" ::: "memory")
#define CP_WAIT2()  asm volatile("cp.async.wait_group 2;" ::: "memory")

__device__ __forceinline__ void mma_f16(float* d,
                                        uint32_t a0, uint32_t a1, uint32_t a2, uint32_t a3,
                                        uint32_t b0, uint32_t b1) {
    asm volatile(
        "mma.sync.aligned.m16n8k16.row.col.f32.f16.f16.f32 "
        "{%0,%1,%2,%3},{%4,%5,%6,%7},{%8,%9},{%0,%1,%2,%3};"
        : "+f"(d[0]), "+f"(d[1]), "+f"(d[2]), "+f"(d[3])
        : "r"(a0), "r"(a1), "r"(a2), "r"(a3), "r"(b0), "r"(b1));
}
__device__ __forceinline__ uint32_t h2u(__half2 h) { return *(uint32_t*)&h; }

// packed fp32x2: q = ab * ef (one instruction, two products)
__device__ __forceinline__ float2 mul2f(ULL ab, ULL ef) {
    ULL q;
    asm("mul.rn.f32x2 %0, %1, %2;" : "=l"(q) : "l"(ab), "l"(ef));
    float2 r;
    asm("mov.b64 {%0,%1}, %2;" : "=f"(r.x), "=f"(r.y) : "l"(q));
    return r;
}
__device__ __forceinline__ ULL pack2f(float x, float y) {
    ULL v; asm("mov.b64 %0, {%1,%2};" : "=l"(v) : "f"(x), "f"(y)); return v;
}
__device__ __forceinline__ ULL ld_s64(uint32_t addr) {
    ULL v; asm volatile("ld.shared.b64 %0, [%1];" : "=l"(v) : "r"(addr)); return v;
}
// fp16-truncation of fp32 (top 10 mantissa bits) — exact float(cvt_rz_f16(v))
// for v in fp16 normal range; used for cheap hi/lo residual split.
__device__ __forceinline__ float trunc16(float v) {
    return __uint_as_float(__float_as_uint(v) & 0xFFFFE000u);
}

// monotone float<->uint encoding for atomicMax
__device__ __forceinline__ unsigned enc_f(float f) {
    unsigned u = __float_as_uint(f);
    return (u & 0x80000000u) ? ~u : (u | 0x80000000u);
}
__device__ __forceinline__ float dec_f(unsigned u) {
    return (u & 0x80000000u) ? __uint_as_float(u ^ 0x80000000u) : __uint_as_float(~u);
}

// ---------------------------------------------------------------------------
// Kernel A: h = input @ W fused with: adj bitmask (ballot), dots, batch max.
// 512 blocks x 8 warps; each warp also converts 256 adj floats -> 8 mask words.
// ---------------------------------------------------------------------------
__global__ void __launch_bounds__(256) gemm_h_kernel(const float* __restrict__ in,
                                                     const float* __restrict__ W,
                                                     const float* __restrict__ av,
                                                     const float* __restrict__ adj) {
    __shared__ float Ws[64 * 64];
    __shared__ float Is[64 * 64];
    __shared__ float red[8];
    const int t = threadIdx.x;
    const int row0 = blockIdx.x * 64;
    const int lane = t & 31;
    const int gw2 = blockIdx.x * 8 + (t >> 5);   // 0..4095, 2 mask jobs each

    // issue adj loads first; DRAM latency hides under staging + sync
    float mv[8];
    const float* mb = adj + (size_t)gw2 * 256;
#pragma unroll
    for (int q = 0; q < 8; q++) mv[q] = __ldg(mb + q * 32 + lane);

    const float4* W4 = (const float4*)W;
    float4* Ws4 = (float4*)Ws;
#pragma unroll
    for (int q = 0; q < 4; q++) Ws4[t + q * 256] = W4[t + q * 256];
    const float4* in4 = (const float4*)(in + row0 * 64);
    float4* Is4 = (float4*)Is;
#pragma unroll
    for (int q = 0; q < 4; q++) Is4[t + q * 256] = in4[t + q * 256];
    __syncthreads();

    // ballot + store mask words (8 consecutive words per warp)
#pragma unroll
    for (int q = 0; q < 8; q++) {
        uint32_t m = __ballot_sync(0xffffffffu, mv[q] > 0.5f);
        if (lane == 0) g_mask[gw2 * 8 + q] = m;
    }

    const int tx = t & 15;
    const int ty = t >> 4;
    float acc[4][4];
#pragma unroll
    for (int i = 0; i < 4; i++)
#pragma unroll
        for (int j = 0; j < 4; j++) acc[i][j] = 0.f;

#pragma unroll
    for (int k = 0; k < 64; k++) {
        const float4 b = *(const float4*)&Ws[k * 64 + 4 * tx];
        const float a0 = Is[(4 * ty + 0) * 64 + k];
        const float a1 = Is[(4 * ty + 1) * 64 + k];
        const float a2 = Is[(4 * ty + 2) * 64 + k];
        const float a3 = Is[(4 * ty + 3) * 64 + k];
        acc[0][0] = fmaf(a0, b.x, acc[0][0]); acc[0][1] = fmaf(a0, b.y, acc[0][1]);
        acc[0][2] = fmaf(a0, b.z, acc[0][2]); acc[0][3] = fmaf(a0, b.w, acc[0][3]);
        acc[1][0] = fmaf(a1, b.x, acc[1][0]); acc[1][1] = fmaf(a1, b.y, acc[1][1]);
        acc[1][2] = fmaf(a1, b.z, acc[1][2]); acc[1][3] = fmaf(a1, b.w, acc[1][3]);
        acc[2][0] = fmaf(a2, b.x, acc[2][0]); acc[2][1] = fmaf(a2, b.y, acc[2][1]);
        acc[2][2] = fmaf(a2, b.z, acc[2][2]); acc[2][3] = fmaf(a2, b.w, acc[2][3]);
        acc[3][0] = fmaf(a3, b.x, acc[3][0]); acc[3][1] = fmaf(a3, b.y, acc[3][1]);
        acc[3][2] = fmaf(a3, b.z, acc[3][2]); acc[3][3] = fmaf(a3, b.w, acc[3][3]);
    }

    const int b = row0 >> 10;
    const int n0 = row0 & 1023;

#pragma unroll
    for (int p = 0; p < 2; p++) {
        const int npair = (n0 + 4 * ty) / 2 + p;
#pragma unroll
        for (int j = 0; j < 4; j++) {
            const float va = acc[2 * p + 0][j];
            const float vb = acc[2 * p + 1][j];
            const __half ha = __float2half_rn(va);
            const __half hb = __float2half_rn(vb);
            uint2 pkv;
            pkv.x = h2u(__halves2half2(ha, hb));
            pkv.y = h2u(__floats2half2_rn(va - __half2float(ha), vb - __half2float(hb)));
            g_hpk[((size_t)b * 64 + 4 * tx + j) * 512 + npair] = pkv;
        }
    }

    float as_[4], ad_[4];
#pragma unroll
    for (int j = 0; j < 4; j++) {
        as_[j] = __ldg(av + 4 * tx + j);
        ad_[j] = __ldg(av + 64 + 4 * tx + j);
    }
    float sdmax = -INFINITY;
#pragma unroll
    for (int i = 0; i < 4; i++) {
        float ss = acc[i][0] * as_[0] + acc[i][1] * as_[1] + acc[i][2] * as_[2] + acc[i][3] * as_[3];
        float sd = acc[i][0] * ad_[0] + acc[i][1] * ad_[1] + acc[i][2] * ad_[2] + acc[i][3] * ad_[3];
#pragma unroll
        for (int o = 8; o; o >>= 1) {
            ss += __shfl_xor_sync(0xffffffffu, ss, o);
            sd += __shfl_xor_sync(0xffffffffu, sd, o);
        }
        if (tx == 0) {
            const int row = row0 + 4 * ty + i;
            g_ssrc[row] = ss;
            g_sdst[row] = sd;
        }
        sdmax = fmaxf(sdmax, sd);
    }
#pragma unroll
    for (int o = 16; o; o >>= 1) sdmax = fmaxf(sdmax, __shfl_xor_sync(0xffffffffu, sdmax, o));
    if ((t & 31) == 0) red[t >> 5] = sdmax;
    __syncthreads();
    if (t == 0) {
        float m = red[0];
#pragma unroll
        for (int i = 1; i < 8; i++) m = fmaxf(m, red[i]);
        atomicMax(&g_smaxu[b], enc_f(m));
    }
}

// ---------------------------------------------------------------------------
// Kernel C: factored-softmax coefficients (elementwise)
// ---------------------------------------------------------------------------
__global__ void __launch_bounds__(256) prep_kernel() {
    const int idx = blockIdx.x * 256 + threadIdx.x;
    const int b = idx >> 10;
    const float S = dec_f(g_smaxu[b]);
    const float ss = g_ssrc[idx];
    const float sd = g_sdst[idx];
    float mm = ss + S; mm = mm >= 0.f ? mm : 0.2f * mm;
    g_AB[idx] = make_float2(__expf(ss - mm), __expf(0.2f * ss - mm));
    g_EF[idx] = make_float2(__expf(sd), __expf(0.2f * sd));
}

// ---------------------------------------------------------------------------
// Kernel D: fused attention. p = max(AE, BF) via f32x2; bit-trunc hi/lo split
// (no unpack cvts on critical path); early-issued cp.async stages; l via
// ones-column MMA; 3xFP16 mma m16n8k16.
// ---------------------------------------------------------------------------
#define PKS 36
#define PKBUF_ELEMS (64 * PKS)
#define SMEM_DYN (4 * PKBUF_ELEMS * 8 + 4 * 64 * 8)
#define ONES2 0x3C003C00u

__global__ void __launch_bounds__(256, 2) attn_kernel(float* __restrict__ out) {
    extern __shared__ char sm[];
    uint2* pkbase = (uint2*)sm;
    float2* efbase = (float2*)(sm + 4 * PKBUF_ELEMS * 8);
    const uint32_t ef_addr0 = smem_u32(efbase);

    const int b = blockIdx.y;
    const int i0 = blockIdx.x * 128;
    const int t = threadIdx.x;
    const int w = t >> 5;
    const int lane = t & 31;
    const int r0 = lane >> 2;
    const int c0 = lane & 3;

    const int irow0 = i0 + w * 16 + r0;
    const int irow1 = irow0 + 8;

    const float2 ab0 = g_AB[b * N_ + irow0];
    const float2 ab1 = g_AB[b * N_ + irow1];
    const ULL AB0 = pack2f(ab0.x, ab0.y);
    const ULL AB1 = pack2f(ab1.x, ab1.y);

    float D[8][4];
#pragma unroll
    for (int nb = 0; nb < 8; nb++)
#pragma unroll
        for (int q = 0; q < 4; q++) D[nb][q] = 0.f;
    float Dl[4] = {0.f, 0.f, 0.f, 0.f};

    const uint32_t* mk0 = g_mask + (size_t)irow0 * 32;
    const uint32_t* mk1 = g_mask + (size_t)irow1 * 32;

    auto stage = [&](int jt) {
        const int buf = jt & 3;
        uint2* pkd = pkbase + buf * PKBUF_ELEMS;
#pragma unroll
        for (int q = 0; q < 4; q++) {
            const int cid = q * 256 + t;
            const int c = cid >> 4;
            const int part = cid & 15;
            cp_async16(smem_u32(&pkd[c * PKS + part * 2]),
                       &g_hpk[((size_t)b * 64 + c) * 512 + jt * 32 + part * 2]);
        }
        if (t < 32)
            cp_async16(smem_u32(&efbase[buf * 64 + t * 2]), &g_EF[b * N_ + jt * 64 + t * 2]);
    };

    stage(0); CP_COMMIT();
    stage(1); CP_COMMIT();
    stage(2); CP_COMMIT();

    uint32_t mw00 = __ldg(mk0 + 0), mw01 = __ldg(mk0 + 1);
    uint32_t mw10 = __ldg(mk1 + 0), mw11 = __ldg(mk1 + 1);

    for (int jt = 0; jt < 16; jt++) {
        CP_WAIT2();
        __syncthreads();

        // issue next stage EARLY so cp.async drains under this tile's compute
        // (safe: buffer (jt+3)&3 == (jt-1)&3 was fully consumed before the sync)
        if (jt + 3 < 16) stage(jt + 3);
        CP_COMMIT();

        const int jw = (jt < 15) ? (jt + 1) * 2 : 0;
        const uint32_t nw00 = __ldg(mk0 + jw), nw01 = __ldg(mk0 + jw + 1);
        const uint32_t nw10 = __ldg(mk1 + jw), nw11 = __ldg(mk1 + jw + 1);

        const int buf = jt & 3;
        const uint2* pkp = pkbase + buf * PKBUF_ELEMS;
        const uint32_t efs = ef_addr0 + buf * 512 + 2 * c0 * 8;

        const uint32_t wsh00 = mw00 >> (2 * c0), wsh01 = mw01 >> (2 * c0);
        const uint32_t wsh10 = mw10 >> (2 * c0), wsh11 = mw11 >> (2 * c0);

#pragma unroll
        for (int ks = 0; ks < 4; ks++) {
            const uint32_t ea_addr = efs + ks * 16 * 8;
            const ULL ea = ld_s64(ea_addr);
            const ULL eb = ld_s64(ea_addr + 8);
            const ULL ec = ld_s64(ea_addr + 64);
            const ULL ed = ld_s64(ea_addr + 72);
            const uint32_t ws0 = (ks < 2) ? wsh00 : wsh01;
            const uint32_t ws1 = (ks < 2) ? wsh10 : wsh11;
            const int bo = (ks & 1) << 4;

            float2 q;
            q = mul2f(AB0, ea); float p00 = fmaxf(q.x, q.y);
            q = mul2f(AB0, eb); float p01 = fmaxf(q.x, q.y);
            q = mul2f(AB0, ec); float p02 = fmaxf(q.x, q.y);
            q = mul2f(AB0, ed); float p03 = fmaxf(q.x, q.y);
            q = mul2f(AB1, ea); float p10 = fmaxf(q.x, q.y);
            q = mul2f(AB1, eb); float p11 = fmaxf(q.x, q.y);
            q = mul2f(AB1, ec); float p12 = fmaxf(q.x, q.y);
            q = mul2f(AB1, ed); float p13 = fmaxf(q.x, q.y);

            p00 = ((ws0 >> (bo + 0)) & 1u) ? p00 : 0.f;
            p01 = ((ws0 >> (bo + 1)) & 1u) ? p01 : 0.f;
            p02 = ((ws0 >> (bo + 8)) & 1u) ? p02 : 0.f;
            p03 = ((ws0 >> (bo + 9)) & 1u) ? p03 : 0.f;
            p10 = ((ws1 >> (bo + 0)) & 1u) ? p10 : 0.f;
            p11 = ((ws1 >> (bo + 1)) & 1u) ? p11 : 0.f;
            p12 = ((ws1 >> (bo + 8)) & 1u) ? p12 : 0.f;
            p13 = ((ws1 >> (bo + 9)) & 1u) ? p13 : 0.f;

            // hi/lo split via bit truncation (LOP3, no cvt-back on the chain)
            const float t00 = trunc16(p00), t01 = trunc16(p01);
            const float t02 = trunc16(p02), t03 = trunc16(p03);
            const float t10 = trunc16(p10), t11 = trunc16(p11);
            const float t12 = trunc16(p12), t13 = trunc16(p13);

            const uint32_t uh0 = h2u(__floats2half2_rn(t00, t01));
            const uint32_t uh1 = h2u(__floats2half2_rn(t10, t11));
            const uint32_t uh2 = h2u(__floats2half2_rn(t02, t03));
            const uint32_t uh3 = h2u(__floats2half2_rn(t12, t13));
            const uint32_t ul0 = h2u(__floats2half2_rn(p00 - t00, p01 - t01));
            const uint32_t ul1 = h2u(__floats2half2_rn(p10 - t10, p11 - t11));
            const uint32_t ul2 = h2u(__floats2half2_rn(p02 - t02, p03 - t03));
            const uint32_t ul3 = h2u(__floats2half2_rn(p12 - t12, p13 - t13));

            // l accumulation via ones-column MMA: Dl[0]=l(irow0), Dl[2]=l(irow1)
            mma_f16(Dl, uh0, uh1, uh2, uh3, ONES2, ONES2);
            mma_f16(Dl, ul0, ul1, ul2, ul3, ONES2, ONES2);

#pragma unroll
            for (int nb = 0; nb < 8; nb++) {
                const int crow = nb * 8 + r0;
                const uint2 bv0 = pkp[crow * PKS + ks * 8 + c0];
                const uint2 bv1 = pkp[crow * PKS + ks * 8 + c0 + 4];
                mma_f16(D[nb], uh0, uh1, uh2, uh3, bv0.x, bv1.x);  // ph * hh
                mma_f16(D[nb], uh0, uh1, uh2, uh3, bv0.y, bv1.y);  // ph * hl
                mma_f16(D[nb], ul0, ul1, ul2, ul3, bv0.x, bv1.x);  // pl * hh
            }
        }

        mw00 = nw00; mw01 = nw01; mw10 = nw10; mw11 = nw11;
    }

    const float inv0 = 1.0f / Dl[0];
    const float inv1 = 1.0f / Dl[2];

    float2* o0 = (float2*)(out + ((size_t)b * N_ + irow0) * C_ + 2 * c0);
    float2* o1 = (float2*)(out + ((size_t)b * N_ + irow1) * C_ + 2 * c0);
#pragma unroll
    for (int nb = 0; nb < 8; nb++) {
        float v0 = D[nb][0] * inv0;
        float v1 = D[nb][1] * inv0;
        float v2 = D[nb][2] * inv1;
        float v3 = D[nb][3] * inv1;
        v0 = v0 > 0.f ? v0 : (__expf(v0) - 1.0f);
        v1 = v1 > 0.f ? v1 : (__expf(v1) - 1.0f);
        v2 = v2 > 0.f ? v2 : (__expf(v2) - 1.0f);
        v3 = v3 > 0.f ? v3 : (__expf(v3) - 1.0f);
        o0[nb * 4] = make_float2(v0, v1);
        o1[nb * 4] = make_float2(v2, v3);
    }
}

// ---------------------------------------------------------------------------
extern "C" void kernel_launch(void* const* d_in, const int* in_sizes, int n_in,
                              void* d_out, int out_size) {
    const float* input = (const float*)d_in[0];  // (32,1024,64)
    const float* adj   = (const float*)d_in[1];  // (1024,1024)
    const float* W     = (const float*)d_in[2];  // (64,64)
    const float* a     = (const float*)d_in[3];  // (128,1)
    float* out = (float*)d_out;

    cudaFuncSetAttribute(attn_kernel, cudaFuncAttributeMaxDynamicSharedMemorySize, SMEM_DYN);

    gemm_h_kernel<<<BN / 64, 256>>>(input, W, a, adj);
    prep_kernel<<<BN / 256, 256>>>();
    attn_kernel<<<dim3(N_ / 128, B_), 256, SMEM_DYN>>>(out);
}

// round 12
// speedup vs baseline: 3.1095x; 1.0441x over previous
#include <cuda_runtime.h>
#include <cuda_fp16.h>
#include <cstdint>
#include <math.h>

#define B_ 32
#define N_ 1024
#define C_ 64
#define BN (B_ * N_)

typedef unsigned long long ULL;

// device-global scratch (allocation-free rule)
// g_hpk: [b][c][tile(16)][permuted slot]: pairs stored so that the two
// B-fragments a thread needs per (kstep,c0) are adjacent (one LDS.128).
__device__ uint2    g_hpk[B_ * C_ * (N_ / 2)];
__device__ float    g_ssrc[BN];
__device__ float    g_sdst[BN];
__device__ unsigned g_smaxu[B_];
__device__ float2   g_AB[BN];                  // (A, B) per row
__device__ float2   g_EF[BN];                  // (E, F) per col
__device__ uint32_t g_mask[N_ * N_ / 32];      // adj>0.5 bitmask

__device__ __forceinline__ uint32_t smem_u32(const void* p) {
    uint32_t a;
    asm("{ .reg .u64 t; cvta.to.shared.u64 t, %1; cvt.u32.u64 %0, t; }" : "=r"(a) : "l"(p));
    return a;
}
__device__ __forceinline__ void cp_async16(uint32_t dst, const void* src) {
    asm volatile("cp.async.cg.shared.global [%0], [%1], 16;" :: "r"(dst), "l"(src));
}
#define CP_COMMIT() asm volatile("cp.async.commit_group;" ::: "memory")
#define CP_WAIT2()  asm volatile("cp.async.wait_group 2;" ::: "memory")

__device__ __forceinline__ void mma_f16(float* d,
                                        uint32_t a0, uint32_t a1, uint32_t a2, uint32_t a3,
                                        uint32_t b0, uint32_t b1) {
    asm volatile(
        "mma.sync.aligned.m16n8k16.row.col.f32.f16.f16.f32 "
        "{%0,%1,%2,%3},{%4,%5,%6,%7},{%8,%9},{%0,%1,%2,%3};"
        : "+f"(d[0]), "+f"(d[1]), "+f"(d[2]), "+f"(d[3])
        : "r"(a0), "r"(a1), "r"(a2), "r"(a3), "r"(b0), "r"(b1));
}
__device__ __forceinline__ uint32_t h2u(__half2 h) { return *(uint32_t*)&h; }

__device__ __forceinline__ float2 mul2f(ULL ab, ULL ef) {
    ULL q;
    asm("mul.rn.f32x2 %0, %1, %2;" : "=l"(q) : "l"(ab), "l"(ef));
    float2 r;
    asm("mov.b64 {%0,%1}, %2;" : "=f"(r.x), "=f"(r.y) : "l"(q));
    return r;
}
__device__ __forceinline__ ULL pack2f(float x, float y) {
    ULL v; asm("mov.b64 %0, {%1,%2};" : "=l"(v) : "f"(x), "f"(y)); return v;
}
__device__ __forceinline__ ULL ld_s64(uint32_t addr) {
    ULL v; asm volatile("ld.shared.b64 %0, [%1];" : "=l"(v) : "r"(addr)); return v;
}
__device__ __forceinline__ float trunc16(float v) {
    return __uint_as_float(__float_as_uint(v) & 0xFFFFE000u);
}
__device__ __forceinline__ unsigned enc_f(float f) {
    unsigned u = __float_as_uint(f);
    return (u & 0x80000000u) ? ~u : (u | 0x80000000u);
}
__device__ __forceinline__ float dec_f(unsigned u) {
    return (u & 0x80000000u) ? __uint_as_float(u ^ 0x80000000u) : __uint_as_float(~u);
}

// ---------------------------------------------------------------------------
// Kernel A: h = input @ W fused with adj bitmask, dots, batch max.
// k-loop vectorized: 8 LDS.128 per 64 FMAs.
// ---------------------------------------------------------------------------
__global__ void __launch_bounds__(256) gemm_h_kernel(const float* __restrict__ in,
                                                     const float* __restrict__ W,
                                                     const float* __restrict__ av,
                                                     const float* __restrict__ adj) {
    __shared__ float Ws[64 * 64];
    __shared__ float Is[64 * 64];
    __shared__ float red[8];
    const int t = threadIdx.x;
    const int row0 = blockIdx.x * 64;
    const int lane = t & 31;
    const int gw2 = blockIdx.x * 8 + (t >> 5);

    // adj loads early; latency hides under staging + sync
    float mv[8];
    const float* mb = adj + (size_t)gw2 * 256;
#pragma unroll
    for (int q = 0; q < 8; q++) mv[q] = __ldg(mb + q * 32 + lane);

    const float4* W4 = (const float4*)W;
    float4* Ws4 = (float4*)Ws;
#pragma unroll
    for (int q = 0; q < 4; q++) Ws4[t + q * 256] = W4[t + q * 256];
    const float4* in4 = (const float4*)(in + row0 * 64);
    float4* Is4 = (float4*)Is;
#pragma unroll
    for (int q = 0; q < 4; q++) Is4[t + q * 256] = in4[t + q * 256];
    __syncthreads();

#pragma unroll
    for (int q = 0; q < 8; q++) {
        uint32_t m = __ballot_sync(0xffffffffu, mv[q] > 0.5f);
        if (lane == 0) g_mask[gw2 * 8 + q] = m;
    }

    const int tx = t & 15;
    const int ty = t >> 4;
    float acc[4][4];
#pragma unroll
    for (int i = 0; i < 4; i++)
#pragma unroll
        for (int j = 0; j < 4; j++) acc[i][j] = 0.f;

#pragma unroll
    for (int k0 = 0; k0 < 64; k0 += 4) {
        const float4 b0 = *(const float4*)&Ws[(k0 + 0) * 64 + 4 * tx];
        const float4 b1 = *(const float4*)&Ws[(k0 + 1) * 64 + 4 * tx];
        const float4 b2 = *(const float4*)&Ws[(k0 + 2) * 64 + 4 * tx];
        const float4 b3 = *(const float4*)&Ws[(k0 + 3) * 64 + 4 * tx];
#pragma unroll
        for (int i = 0; i < 4; i++) {
            const float4 a = *(const float4*)&Is[(4 * ty + i) * 64 + k0];
            acc[i][0] = fmaf(a.x, b0.x, acc[i][0]);
            acc[i][1] = fmaf(a.x, b0.y, acc[i][1]);
            acc[i][2] = fmaf(a.x, b0.z, acc[i][2]);
            acc[i][3] = fmaf(a.x, b0.w, acc[i][3]);
            acc[i][0] = fmaf(a.y, b1.x, acc[i][0]);
            acc[i][1] = fmaf(a.y, b1.y, acc[i][1]);
            acc[i][2] = fmaf(a.y, b1.z, acc[i][2]);
            acc[i][3] = fmaf(a.y, b1.w, acc[i][3]);
            acc[i][0] = fmaf(a.z, b2.x, acc[i][0]);
            acc[i][1] = fmaf(a.z, b2.y, acc[i][1]);
            acc[i][2] = fmaf(a.z, b2.z, acc[i][2]);
            acc[i][3] = fmaf(a.z, b2.w, acc[i][3]);
            acc[i][0] = fmaf(a.w, b3.x, acc[i][0]);
            acc[i][1] = fmaf(a.w, b3.y, acc[i][1]);
            acc[i][2] = fmaf(a.w, b3.z, acc[i][2]);
            acc[i][3] = fmaf(a.w, b3.w, acc[i][3]);
        }
    }

    const int b = row0 >> 10;
    const int n0 = row0 & 1023;

    // packed fp16 hi/lo pairs, written to the PERMUTED slot so the consumer
    // can fetch both k-fragments with one LDS.128.
#pragma unroll
    for (int p = 0; p < 2; p++) {
        const int q = 2 * ty + p;                                   // tile-local pair
        const int newq = ((q >> 3) * 4 + (q & 3)) * 2 + ((q >> 2) & 1);
#pragma unroll
        for (int j = 0; j < 4; j++) {
            const float va = acc[2 * p + 0][j];
            const float vb = acc[2 * p + 1][j];
            const __half ha = __float2half_rn(va);
            const __half hb = __float2half_rn(vb);
            uint2 pkv;
            pkv.x = h2u(__halves2half2(ha, hb));
            pkv.y = h2u(__floats2half2_rn(va - __half2float(ha), vb - __half2float(hb)));
            g_hpk[((size_t)b * 64 + 4 * tx + j) * 512 + n0 / 2 + newq] = pkv;
        }
    }

    float as_[4], ad_[4];
#pragma unroll
    for (int j = 0; j < 4; j++) {
        as_[j] = __ldg(av + 4 * tx + j);
        ad_[j] = __ldg(av + 64 + 4 * tx + j);
    }
    float sdmax = -INFINITY;
#pragma unroll
    for (int i = 0; i < 4; i++) {
        float ss = acc[i][0] * as_[0] + acc[i][1] * as_[1] + acc[i][2] * as_[2] + acc[i][3] * as_[3];
        float sd = acc[i][0] * ad_[0] + acc[i][1] * ad_[1] + acc[i][2] * ad_[2] + acc[i][3] * ad_[3];
#pragma unroll
        for (int o = 8; o; o >>= 1) {
            ss += __shfl_xor_sync(0xffffffffu, ss, o);
            sd += __shfl_xor_sync(0xffffffffu, sd, o);
        }
        if (tx == 0) {
            const int row = row0 + 4 * ty + i;
            g_ssrc[row] = ss;
            g_sdst[row] = sd;
        }
        sdmax = fmaxf(sdmax, sd);
    }
#pragma unroll
    for (int o = 16; o; o >>= 1) sdmax = fmaxf(sdmax, __shfl_xor_sync(0xffffffffu, sdmax, o));
    if ((t & 31) == 0) red[t >> 5] = sdmax;
    __syncthreads();
    if (t == 0) {
        float m = red[0];
#pragma unroll
        for (int i = 1; i < 8; i++) m = fmaxf(m, red[i]);
        atomicMax(&g_smaxu[b], enc_f(m));
    }
}

// ---------------------------------------------------------------------------
// Kernel C: factored-softmax coefficients (elementwise)
// ---------------------------------------------------------------------------
__global__ void __launch_bounds__(256) prep_kernel() {
    const int idx = blockIdx.x * 256 + threadIdx.x;
    const int b = idx >> 10;
    const float S = dec_f(g_smaxu[b]);
    const float ss = g_ssrc[idx];
    const float sd = g_sdst[idx];
    float mm = ss + S; mm = mm >= 0.f ? mm : 0.2f * mm;
    g_AB[idx] = make_float2(__expf(ss - mm), __expf(0.2f * ss - mm));
    g_EF[idx] = make_float2(__expf(sd), __expf(0.2f * sd));
}

// ---------------------------------------------------------------------------
// Kernel D: fused attention. LDS.128 packed B-fragments (PKS4=20 stride,
// phase-conflict-free), single ones-MMA for l, 3xFP16 mma m16n8k16.
// ---------------------------------------------------------------------------
#define PKS4 20                              // uint4 stride per c-row
#define PKBUF4 (64 * PKS4)                   // uint4 per buffer (1280)
#define SMEM_DYN (4 * PKBUF4 * 16 + 4 * 64 * 8)
#define ONES2 0x3C003C00u

__global__ void __launch_bounds__(256, 2) attn_kernel(float* __restrict__ out) {
    extern __shared__ char sm[];
    uint4* pkbase = (uint4*)sm;
    float2* efbase = (float2*)(sm + 4 * PKBUF4 * 16);
    const uint32_t ef_addr0 = smem_u32(efbase);

    const int b = blockIdx.y;
    const int i0 = blockIdx.x * 128;
    const int t = threadIdx.x;
    const int w = t >> 5;
    const int lane = t & 31;
    const int r0 = lane >> 2;
    const int c0 = lane & 3;

    const int irow0 = i0 + w * 16 + r0;
    const int irow1 = irow0 + 8;

    const float2 ab0 = g_AB[b * N_ + irow0];
    const float2 ab1 = g_AB[b * N_ + irow1];
    const ULL AB0 = pack2f(ab0.x, ab0.y);
    const ULL AB1 = pack2f(ab1.x, ab1.y);

    float D[8][4];
#pragma unroll
    for (int nb = 0; nb < 8; nb++)
#pragma unroll
        for (int q = 0; q < 4; q++) D[nb][q] = 0.f;
    float Dl[4] = {0.f, 0.f, 0.f, 0.f};

    const uint32_t* mk0 = g_mask + (size_t)irow0 * 32;
    const uint32_t* mk1 = g_mask + (size_t)irow1 * 32;

    auto stage = [&](int jt) {
        const int buf = jt & 3;
        uint4* pkd = pkbase + buf * PKBUF4;
#pragma unroll
        for (int q = 0; q < 4; q++) {
            const int cid = q * 256 + t;       // 1024 chunks of 16B
            const int c = cid >> 4;
            const int part = cid & 15;
            cp_async16(smem_u32(&pkd[c * PKS4 + part]),
                       &g_hpk[((size_t)b * 64 + c) * 512 + jt * 32 + part * 2]);
        }
        if (t < 32)
            cp_async16(smem_u32(&efbase[buf * 64 + t * 2]), &g_EF[b * N_ + jt * 64 + t * 2]);
    };

    stage(0); CP_COMMIT();
    stage(1); CP_COMMIT();
    stage(2); CP_COMMIT();

    uint32_t mw00 = __ldg(mk0 + 0), mw01 = __ldg(mk0 + 1);
    uint32_t mw10 = __ldg(mk1 + 0), mw11 = __ldg(mk1 + 1);

    for (int jt = 0; jt < 16; jt++) {
        CP_WAIT2();
        __syncthreads();

        if (jt + 3 < 16) stage(jt + 3);
        CP_COMMIT();

        const int jw = (jt < 15) ? (jt + 1) * 2 : 0;
        const uint32_t nw00 = __ldg(mk0 + jw), nw01 = __ldg(mk0 + jw + 1);
        const uint32_t nw10 = __ldg(mk1 + jw), nw11 = __ldg(mk1 + jw + 1);

        const int buf = jt & 3;
        const uint4* pkp = pkbase + buf * PKBUF4;
        const uint32_t efs = ef_addr0 + buf * 512 + 2 * c0 * 8;

        const uint32_t wsh00 = mw00 >> (2 * c0), wsh01 = mw01 >> (2 * c0);
        const uint32_t wsh10 = mw10 >> (2 * c0), wsh11 = mw11 >> (2 * c0);

#pragma unroll
        for (int ks = 0; ks < 4; ks++) {
            const uint32_t ea_addr = efs + ks * 16 * 8;
            const ULL ea = ld_s64(ea_addr);
            const ULL eb = ld_s64(ea_addr + 8);
            const ULL ec = ld_s64(ea_addr + 64);
            const ULL ed = ld_s64(ea_addr + 72);
            const uint32_t ws0 = (ks < 2) ? wsh00 : wsh01;
            const uint32_t ws1 = (ks < 2) ? wsh10 : wsh11;
            const int bo = (ks & 1) << 4;

            float2 q;
            q = mul2f(AB0, ea); float p00 = fmaxf(q.x, q.y);
            q = mul2f(AB0, eb); float p01 = fmaxf(q.x, q.y);
            q = mul2f(AB0, ec); float p02 = fmaxf(q.x, q.y);
            q = mul2f(AB0, ed); float p03 = fmaxf(q.x, q.y);
            q = mul2f(AB1, ea); float p10 = fmaxf(q.x, q.y);
            q = mul2f(AB1, eb); float p11 = fmaxf(q.x, q.y);
            q = mul2f(AB1, ec); float p12 = fmaxf(q.x, q.y);
            q = mul2f(AB1, ed); float p13 = fmaxf(q.x, q.y);

            p00 = ((ws0 >> (bo + 0)) & 1u) ? p00 : 0.f;
            p01 = ((ws0 >> (bo + 1)) & 1u) ? p01 : 0.f;
            p02 = ((ws0 >> (bo + 8)) & 1u) ? p02 : 0.f;
            p03 = ((ws0 >> (bo + 9)) & 1u) ? p03 : 0.f;
            p10 = ((ws1 >> (bo + 0)) & 1u) ? p10 : 0.f;
            p11 = ((ws1 >> (bo + 1)) & 1u) ? p11 : 0.f;
            p12 = ((ws1 >> (bo + 8)) & 1u) ? p12 : 0.f;
            p13 = ((ws1 >> (bo + 9)) & 1u) ? p13 : 0.f;

            const float t00 = trunc16(p00), t01 = trunc16(p01);
            const float t02 = trunc16(p02), t03 = trunc16(p03);
            const float t10 = trunc16(p10), t11 = trunc16(p11);
            const float t12 = trunc16(p12), t13 = trunc16(p13);

            const uint32_t uh0 = h2u(__floats2half2_rn(t00, t01));
            const uint32_t uh1 = h2u(__floats2half2_rn(t10, t11));
            const uint32_t uh2 = h2u(__floats2half2_rn(t02, t03));
            const uint32_t uh3 = h2u(__floats2half2_rn(t12, t13));
            const uint32_t ul0 = h2u(__floats2half2_rn(p00 - t00, p01 - t01));
            const uint32_t ul1 = h2u(__floats2half2_rn(p10 - t10, p11 - t11));
            const uint32_t ul2 = h2u(__floats2half2_rn(p02 - t02, p03 - t03));
            const uint32_t ul3 = h2u(__floats2half2_rn(p12 - t12, p13 - t13));

            // l from ph only (|Σpl|/l ~ 2^-11/sqrt(n) ≈ 2e-5, well under gate)
            mma_f16(Dl, uh0, uh1, uh2, uh3, ONES2, ONES2);

#pragma unroll
            for (int nb = 0; nb < 8; nb++) {
                const uint4 bv = pkp[(nb * 8 + r0) * PKS4 + ks * 4 + c0];
                mma_f16(D[nb], uh0, uh1, uh2, uh3, bv.x, bv.z);  // ph * hh
                mma_f16(D[nb], uh0, uh1, uh2, uh3, bv.y, bv.w);  // ph * hl
                mma_f16(D[nb], ul0, ul1, ul2, ul3, bv.x, bv.z);  // pl * hh
            }
        }

        mw00 = nw00; mw01 = nw01; mw10 = nw10; mw11 = nw11;
    }

    const float inv0 = 1.0f / Dl[0];
    const float inv1 = 1.0f / Dl[2];

    float2* o0 = (float2*)(out + ((size_t)b * N_ + irow0) * C_ + 2 * c0);
    float2* o1 = (float2*)(out + ((size_t)b * N_ + irow1) * C_ + 2 * c0);
#pragma unroll
    for (int nb = 0; nb < 8; nb++) {
        float v0 = D[nb][0] * inv0;
        float v1 = D[nb][1] * inv0;
        float v2 = D[nb][2] * inv1;
        float v3 = D[nb][3] * inv1;
        v0 = v0 > 0.f ? v0 : (__expf(v0) - 1.0f);
        v1 = v1 > 0.f ? v1 : (__expf(v1) - 1.0f);
        v2 = v2 > 0.f ? v2 : (__expf(v2) - 1.0f);
        v3 = v3 > 0.f ? v3 : (__expf(v3) - 1.0f);
        o0[nb * 4] = make_float2(v0, v1);
        o1[nb * 4] = make_float2(v2, v3);
    }
}

// ---------------------------------------------------------------------------
extern "C" void kernel_launch(void* const* d_in, const int* in_sizes, int n_in,
                              void* d_out, int out_size) {
    const float* input = (const float*)d_in[0];  // (32,1024,64)
    const float* adj   = (const float*)d_in[1];  // (1024,1024)
    const float* W     = (const float*)d_in[2];  // (64,64)
    const float* a     = (const float*)d_in[3];  // (128,1)
    float* out = (float*)d_out;

    cudaFuncSetAttribute(attn_kernel, cudaFuncAttributeMaxDynamicSharedMemorySize, SMEM_DYN);

    gemm_h_kernel<<<BN / 64, 256>>>(input, W, a, adj);
    prep_kernel<<<BN / 256, 256>>>();
    attn_kernel<<<dim3(N_ / 128, B_), 256, SMEM_DYN>>>(out);
}

// round 13
// speedup vs baseline: 3.1308x; 1.0068x over previous
#include <cuda_runtime.h>
#include <cuda_fp16.h>
#include <cstdint>
#include <math.h>

#define B_ 32
#define N_ 1024
#define C_ 64
#define BN (B_ * N_)

typedef unsigned long long ULL;

// device-global scratch (allocation-free rule)
// g_hpk: [b][c][permuted pair slot]: (hh2, hl2) fp16 pairs, slots arranged so
// the consumer fetches both k-fragments of an MMA with one LDS.128.
__device__ uint2    g_hpk[B_ * C_ * (N_ / 2)];
__device__ float    g_ssrc[BN];
__device__ float    g_sdst[BN];
__device__ unsigned g_smaxu[B_];
__device__ float2   g_AB[BN];                  // (A, B) per row
__device__ float2   g_EF[BN];                  // (E, F) per col
__device__ uint32_t g_mask[N_ * N_ / 32];      // adj>0.5 bitmask

__device__ __forceinline__ uint32_t smem_u32(const void* p) {
    uint32_t a;
    asm("{ .reg .u64 t; cvta.to.shared.u64 t, %1; cvt.u32.u64 %0, t; }" : "=r"(a) : "l"(p));
    return a;
}
__device__ __forceinline__ void cp_async16(uint32_t dst, const void* src) {
    asm volatile("cp.async.cg.shared.global [%0], [%1], 16;" :: "r"(dst), "l"(src));
}
#define CP_COMMIT() asm volatile("cp.async.commit_group;" ::: "memory")
#define CP_WAIT2()  asm volatile("cp.async.wait_group 2;" ::: "memory")

__device__ __forceinline__ void mma_f16(float* d,
                                        uint32_t a0, uint32_t a1, uint32_t a2, uint32_t a3,
                                        uint32_t b0, uint32_t b1) {
    asm volatile(
        "mma.sync.aligned.m16n8k16.row.col.f32.f16.f16.f32 "
        "{%0,%1,%2,%3},{%4,%5,%6,%7},{%8,%9},{%0,%1,%2,%3};"
        : "+f"(d[0]), "+f"(d[1]), "+f"(d[2]), "+f"(d[3])
        : "r"(a0), "r"(a1), "r"(a2), "r"(a3), "r"(b0), "r"(b1));
}
__device__ __forceinline__ uint32_t h2u(__half2 h) { return *(uint32_t*)&h; }

__device__ __forceinline__ float2 mul2f(ULL ab, ULL ef) {
    ULL q;
    asm("mul.rn.f32x2 %0, %1, %2;" : "=l"(q) : "l"(ab), "l"(ef));
    float2 r;
    asm("mov.b64 {%0,%1}, %2;" : "=f"(r.x), "=f"(r.y) : "l"(q));
    return r;
}
__device__ __forceinline__ ULL pack2f(float x, float y) {
    ULL v; asm("mov.b64 %0, {%1,%2};" : "=l"(v) : "f"(x), "f"(y)); return v;
}
__device__ __forceinline__ ULL ld_s64(uint32_t addr) {
    ULL v; asm volatile("ld.shared.b64 %0, [%1];" : "=l"(v) : "r"(addr)); return v;
}
__device__ __forceinline__ float trunc16(float v) {
    return __uint_as_float(__float_as_uint(v) & 0xFFFFE000u);
}
__device__ __forceinline__ unsigned enc_f(float f) {
    unsigned u = __float_as_uint(f);
    return (u & 0x80000000u) ? ~u : (u | 0x80000000u);
}
__device__ __forceinline__ float dec_f(unsigned u) {
    return (u & 0x80000000u) ? __uint_as_float(u ^ 0x80000000u) : __uint_as_float(~u);
}

// ---------------------------------------------------------------------------
// Kernel A: h = input @ W fused with adj bitmask, dots, batch max.
// hpk output staged in smem and written COALESCED (fixes the 4KB-stride
// scattered-uint2 write amplification that dominated this kernel).
// ---------------------------------------------------------------------------
#define TPS 33  // uint2 stride of the smem stage tile (pad 1 vs 32)

__global__ void __launch_bounds__(256) gemm_h_kernel(const float* __restrict__ in,
                                                     const float* __restrict__ W,
                                                     const float* __restrict__ av,
                                                     const float* __restrict__ adj) {
    __shared__ float smem_f[2 * 64 * 64];   // Ws | Is, later reused as stage tile
    __shared__ float red[8];
    float* Ws = smem_f;
    float* Is = smem_f + 4096;
    uint2* tile = (uint2*)smem_f;           // 64 x TPS uint2 (16.9KB)

    const int t = threadIdx.x;
    const int row0 = blockIdx.x * 64;
    const int lane = t & 31;
    const int gw2 = blockIdx.x * 8 + (t >> 5);

    // adj loads early; latency hides under staging + sync
    float mv[8];
    const float* mb = adj + (size_t)gw2 * 256;
#pragma unroll
    for (int q = 0; q < 8; q++) mv[q] = __ldg(mb + q * 32 + lane);

    const float4* W4 = (const float4*)W;
    float4* Ws4 = (float4*)Ws;
#pragma unroll
    for (int q = 0; q < 4; q++) Ws4[t + q * 256] = W4[t + q * 256];
    const float4* in4 = (const float4*)(in + row0 * 64);
    float4* Is4 = (float4*)Is;
#pragma unroll
    for (int q = 0; q < 4; q++) Is4[t + q * 256] = in4[t + q * 256];
    __syncthreads();

#pragma unroll
    for (int q = 0; q < 8; q++) {
        uint32_t m = __ballot_sync(0xffffffffu, mv[q] > 0.5f);
        if (lane == 0) g_mask[gw2 * 8 + q] = m;
    }

    const int tx = t & 15;
    const int ty = t >> 4;
    float acc[4][4];
#pragma unroll
    for (int i = 0; i < 4; i++)
#pragma unroll
        for (int j = 0; j < 4; j++) acc[i][j] = 0.f;

#pragma unroll
    for (int k0 = 0; k0 < 64; k0 += 4) {
        const float4 b0 = *(const float4*)&Ws[(k0 + 0) * 64 + 4 * tx];
        const float4 b1 = *(const float4*)&Ws[(k0 + 1) * 64 + 4 * tx];
        const float4 b2 = *(const float4*)&Ws[(k0 + 2) * 64 + 4 * tx];
        const float4 b3 = *(const float4*)&Ws[(k0 + 3) * 64 + 4 * tx];
#pragma unroll
        for (int i = 0; i < 4; i++) {
            const float4 a = *(const float4*)&Is[(4 * ty + i) * 64 + k0];
            acc[i][0] = fmaf(a.x, b0.x, acc[i][0]);
            acc[i][1] = fmaf(a.x, b0.y, acc[i][1]);
            acc[i][2] = fmaf(a.x, b0.z, acc[i][2]);
            acc[i][3] = fmaf(a.x, b0.w, acc[i][3]);
            acc[i][0] = fmaf(a.y, b1.x, acc[i][0]);
            acc[i][1] = fmaf(a.y, b1.y, acc[i][1]);
            acc[i][2] = fmaf(a.y, b1.z, acc[i][2]);
            acc[i][3] = fmaf(a.y, b1.w, acc[i][3]);
            acc[i][0] = fmaf(a.z, b2.x, acc[i][0]);
            acc[i][1] = fmaf(a.z, b2.y, acc[i][1]);
            acc[i][2] = fmaf(a.z, b2.z, acc[i][2]);
            acc[i][3] = fmaf(a.z, b2.w, acc[i][3]);
            acc[i][0] = fmaf(a.w, b3.x, acc[i][0]);
            acc[i][1] = fmaf(a.w, b3.y, acc[i][1]);
            acc[i][2] = fmaf(a.w, b3.z, acc[i][2]);
            acc[i][3] = fmaf(a.w, b3.w, acc[i][3]);
        }
    }

    const int b = row0 >> 10;
    const int n0 = row0 & 1023;

    // dots first (uses only registers), then reuse smem for the stage tile
    float as_[4], ad_[4];
#pragma unroll
    for (int j = 0; j < 4; j++) {
        as_[j] = __ldg(av + 4 * tx + j);
        ad_[j] = __ldg(av + 64 + 4 * tx + j);
    }
    float sdmax = -INFINITY;
#pragma unroll
    for (int i = 0; i < 4; i++) {
        float ss = acc[i][0] * as_[0] + acc[i][1] * as_[1] + acc[i][2] * as_[2] + acc[i][3] * as_[3];
        float sd = acc[i][0] * ad_[0] + acc[i][1] * ad_[1] + acc[i][2] * ad_[2] + acc[i][3] * ad_[3];
#pragma unroll
        for (int o = 8; o; o >>= 1) {
            ss += __shfl_xor_sync(0xffffffffu, ss, o);
            sd += __shfl_xor_sync(0xffffffffu, sd, o);
        }
        if (tx == 0) {
            const int row = row0 + 4 * ty + i;
            g_ssrc[row] = ss;
            g_sdst[row] = sd;
        }
        sdmax = fmaxf(sdmax, sd);
    }
#pragma unroll
    for (int o = 16; o; o >>= 1) sdmax = fmaxf(sdmax, __shfl_xor_sync(0xffffffffu, sdmax, o));
    if ((t & 31) == 0) red[t >> 5] = sdmax;

    __syncthreads();  // all k-loop smem reads done; safe to overwrite with tile
    if (t == 0) {
        float m = red[0];
#pragma unroll
        for (int i = 1; i < 8; i++) m = fmaxf(m, red[i]);
        atomicMax(&g_smaxu[b], enc_f(m));
    }

    // stage hpk pairs into smem at the PERMUTED slot
#pragma unroll
    for (int p = 0; p < 2; p++) {
        const int q = 2 * ty + p;  // pair index within 64-row tile (0..31)
        const int newq = ((q >> 3) * 4 + (q & 3)) * 2 + ((q >> 2) & 1);
#pragma unroll
        for (int j = 0; j < 4; j++) {
            const float va = acc[2 * p + 0][j];
            const float vb = acc[2 * p + 1][j];
            const __half ha = __float2half_rn(va);
            const __half hb = __float2half_rn(vb);
            uint2 pkv;
            pkv.x = h2u(__halves2half2(ha, hb));
            pkv.y = h2u(__floats2half2_rn(va - __half2float(ha), vb - __half2float(hb)));
            tile[(4 * tx + j) * TPS + newq] = pkv;
        }
    }
    __syncthreads();

    // coalesced copy out: warp covers one 256B chunk (c-row) per iteration
#pragma unroll
    for (int i = 0; i < 8; i++) {
        const int e = t + 256 * i;       // 0..2047
        const int c = e >> 5;
        const int pr = e & 31;
        g_hpk[((size_t)b * 64 + c) * 512 + n0 / 2 + pr] = tile[c * TPS + pr];
    }
}

// ---------------------------------------------------------------------------
// Kernel C: factored-softmax coefficients (elementwise)
// ---------------------------------------------------------------------------
__global__ void __launch_bounds__(256) prep_kernel() {
    const int idx = blockIdx.x * 256 + threadIdx.x;
    const int b = idx >> 10;
    const float S = dec_f(g_smaxu[b]);
    const float ss = g_ssrc[idx];
    const float sd = g_sdst[idx];
    float mm = ss + S; mm = mm >= 0.f ? mm : 0.2f * mm;
    g_AB[idx] = make_float2(__expf(ss - mm), __expf(0.2f * ss - mm));
    g_EF[idx] = make_float2(__expf(sd), __expf(0.2f * sd));
}

// ---------------------------------------------------------------------------
// Kernel D: fused attention. LDS.128 packed B-fragments, l via TWO ones-MMAs
// (ph and pl — restores rel_err to ~1e-6), 3xFP16 mma m16n8k16.
// ---------------------------------------------------------------------------
#define PKS4 20                              // uint4 stride per c-row
#define PKBUF4 (64 * PKS4)                   // uint4 per buffer (1280)
#define SMEM_DYN (4 * PKBUF4 * 16 + 4 * 64 * 8)
#define ONES2 0x3C003C00u

__global__ void __launch_bounds__(256, 2) attn_kernel(float* __restrict__ out) {
    extern __shared__ char sm[];
    uint4* pkbase = (uint4*)sm;
    float2* efbase = (float2*)(sm + 4 * PKBUF4 * 16);
    const uint32_t ef_addr0 = smem_u32(efbase);

    const int b = blockIdx.y;
    const int i0 = blockIdx.x * 128;
    const int t = threadIdx.x;
    const int w = t >> 5;
    const int lane = t & 31;
    const int r0 = lane >> 2;
    const int c0 = lane & 3;

    const int irow0 = i0 + w * 16 + r0;
    const int irow1 = irow0 + 8;

    const float2 ab0 = g_AB[b * N_ + irow0];
    const float2 ab1 = g_AB[b * N_ + irow1];
    const ULL AB0 = pack2f(ab0.x, ab0.y);
    const ULL AB1 = pack2f(ab1.x, ab1.y);

    float D[8][4];
#pragma unroll
    for (int nb = 0; nb < 8; nb++)
#pragma unroll
        for (int q = 0; q < 4; q++) D[nb][q] = 0.f;
    float Dl[4] = {0.f, 0.f, 0.f, 0.f};

    const uint32_t* mk0 = g_mask + (size_t)irow0 * 32;
    const uint32_t* mk1 = g_mask + (size_t)irow1 * 32;

    auto stage = [&](int jt) {
        const int buf = jt & 3;
        uint4* pkd = pkbase + buf * PKBUF4;
#pragma unroll
        for (int q = 0; q < 4; q++) {
            const int cid = q * 256 + t;
            const int c = cid >> 4;
            const int part = cid & 15;
            cp_async16(smem_u32(&pkd[c * PKS4 + part]),
                       &g_hpk[((size_t)b * 64 + c) * 512 + jt * 32 + part * 2]);
        }
        if (t < 32)
            cp_async16(smem_u32(&efbase[buf * 64 + t * 2]), &g_EF[b * N_ + jt * 64 + t * 2]);
    };

    stage(0); CP_COMMIT();
    stage(1); CP_COMMIT();
    stage(2); CP_COMMIT();

    uint32_t mw00 = __ldg(mk0 + 0), mw01 = __ldg(mk0 + 1);
    uint32_t mw10 = __ldg(mk1 + 0), mw11 = __ldg(mk1 + 1);

    for (int jt = 0; jt < 16; jt++) {
        CP_WAIT2();
        __syncthreads();

        if (jt + 3 < 16) stage(jt + 3);
        CP_COMMIT();

        const int jw = (jt < 15) ? (jt + 1) * 2 : 0;
        const uint32_t nw00 = __ldg(mk0 + jw), nw01 = __ldg(mk0 + jw + 1);
        const uint32_t nw10 = __ldg(mk1 + jw), nw11 = __ldg(mk1 + jw + 1);

        const int buf = jt & 3;
        const uint4* pkp = pkbase + buf * PKBUF4;
        const uint32_t efs = ef_addr0 + buf * 512 + 2 * c0 * 8;

        const uint32_t wsh00 = mw00 >> (2 * c0), wsh01 = mw01 >> (2 * c0);
        const uint32_t wsh10 = mw10 >> (2 * c0), wsh11 = mw11 >> (2 * c0);

#pragma unroll
        for (int ks = 0; ks < 4; ks++) {
            const uint32_t ea_addr = efs + ks * 16 * 8;
            const ULL ea = ld_s64(ea_addr);
            const ULL eb = ld_s64(ea_addr + 8);
            const ULL ec = ld_s64(ea_addr + 64);
            const ULL ed = ld_s64(ea_addr + 72);
            const uint32_t ws0 = (ks < 2) ? wsh00 : wsh01;
            const uint32_t ws1 = (ks < 2) ? wsh10 : wsh11;
            const int bo = (ks & 1) << 4;

            float2 q;
            q = mul2f(AB0, ea); float p00 = fmaxf(q.x, q.y);
            q = mul2f(AB0, eb); float p01 = fmaxf(q.x, q.y);
            q = mul2f(AB0, ec); float p02 = fmaxf(q.x, q.y);
            q = mul2f(AB0, ed); float p03 = fmaxf(q.x, q.y);
            q = mul2f(AB1, ea); float p10 = fmaxf(q.x, q.y);
            q = mul2f(AB1, eb); float p11 = fmaxf(q.x, q.y);
            q = mul2f(AB1, ec); float p12 = fmaxf(q.x, q.y);
            q = mul2f(AB1, ed); float p13 = fmaxf(q.x, q.y);

            p00 = ((ws0 >> (bo + 0)) & 1u) ? p00 : 0.f;
            p01 = ((ws0 >> (bo + 1)) & 1u) ? p01 : 0.f;
            p02 = ((ws0 >> (bo + 8)) & 1u) ? p02 : 0.f;
            p03 = ((ws0 >> (bo + 9)) & 1u) ? p03 : 0.f;
            p10 = ((ws1 >> (bo + 0)) & 1u) ? p10 : 0.f;
            p11 = ((ws1 >> (bo + 1)) & 1u) ? p11 : 0.f;
            p12 = ((ws1 >> (bo + 8)) & 1u) ? p12 : 0.f;
            p13 = ((ws1 >> (bo + 9)) & 1u) ? p13 : 0.f;

            const float t00 = trunc16(p00), t01 = trunc16(p01);
            const float t02 = trunc16(p02), t03 = trunc16(p03);
            const float t10 = trunc16(p10), t11 = trunc16(p11);
            const float t12 = trunc16(p12), t13 = trunc16(p13);

            const uint32_t uh0 = h2u(__floats2half2_rn(t00, t01));
            const uint32_t uh1 = h2u(__floats2half2_rn(t10, t11));
            const uint32_t uh2 = h2u(__floats2half2_rn(t02, t03));
            const uint32_t uh3 = h2u(__floats2half2_rn(t12, t13));
            const uint32_t ul0 = h2u(__floats2half2_rn(p00 - t00, p01 - t01));
            const uint32_t ul1 = h2u(__floats2half2_rn(p10 - t10, p11 - t11));
            const uint32_t ul2 = h2u(__floats2half2_rn(p02 - t02, p03 - t03));
            const uint32_t ul3 = h2u(__floats2half2_rn(p12 - t12, p13 - t13));

            // l = Σ(ph + pl): BOTH ones-MMAs (R12's ph-only gave rel_err 3e-4,
            // too close to the 1e-3 gate)
            mma_f16(Dl, uh0, uh1, uh2, uh3, ONES2, ONES2);
            mma_f16(Dl, ul0, ul1, ul2, ul3, ONES2, ONES2);

#pragma unroll
            for (int nb = 0; nb < 8; nb++) {
                const uint4 bv = pkp[(nb * 8 + r0) * PKS4 + ks * 4 + c0];
                mma_f16(D[nb], uh0, uh1, uh2, uh3, bv.x, bv.z);  // ph * hh
                mma_f16(D[nb], uh0, uh1, uh2, uh3, bv.y, bv.w);  // ph * hl
                mma_f16(D[nb], ul0, ul1, ul2, ul3, bv.x, bv.z);  // pl * hh
            }
        }

        mw00 = nw00; mw01 = nw01; mw10 = nw10; mw11 = nw11;
    }

    const float inv0 = 1.0f / Dl[0];
    const float inv1 = 1.0f / Dl[2];

    float2* o0 = (float2*)(out + ((size_t)b * N_ + irow0) * C_ + 2 * c0);
    float2* o1 = (float2*)(out + ((size_t)b * N_ + irow1) * C_ + 2 * c0);
#pragma unroll
    for (int nb = 0; nb < 8; nb++) {
        float v0 = D[nb][0] * inv0;
        float v1 = D[nb][1] * inv0;
        float v2 = D[nb][2] * inv1;
        float v3 = D[nb][3] * inv1;
        v0 = v0 > 0.f ? v0 : (__expf(v0) - 1.0f);
        v1 = v1 > 0.f ? v1 : (__expf(v1) - 1.0f);
        v2 = v2 > 0.f ? v2 : (__expf(v2) - 1.0f);
        v3 = v3 > 0.f ? v3 : (__expf(v3) - 1.0f);
        o0[nb * 4] = make_float2(v0, v1);
        o1[nb * 4] = make_float2(v2, v3);
    }
}

// ---------------------------------------------------------------------------
extern "C" void kernel_launch(void* const* d_in, const int* in_sizes, int n_in,
                              void* d_out, int out_size) {
    const float* input = (const float*)d_in[0];  // (32,1024,64)
    const float* adj   = (const float*)d_in[1];  // (1024,1024)
    const float* W     = (const float*)d_in[2];  // (64,64)
    const float* a     = (const float*)d_in[3];  // (128,1)
    float* out = (float*)d_out;

    cudaFuncSetAttribute(attn_kernel, cudaFuncAttributeMaxDynamicSharedMemorySize, SMEM_DYN);

    gemm_h_kernel<<<BN / 64, 256>>>(input, W, a, adj);
    prep_kernel<<<BN / 256, 256>>>();
    attn_kernel<<<dim3(N_ / 128, B_), 256, SMEM_DYN>>>(out);
}

// round 14
// speedup vs baseline: 3.2091x; 1.0250x over previous
#include <cuda_runtime.h>
#include <cuda_fp16.h>
#include <cstdint>
#include <math.h>

#define B_ 32
#define N_ 1024
#define C_ 64
#define BN (B_ * N_)

typedef unsigned long long ULL;

// device-global scratch (allocation-free rule)
// g_hpk4: [b][c][uint4 slot]: each uint4 = 2 consecutive permuted uint2 pair
// slots (hh2, hl2) — consumer fetches a full MMA B-fragment with one LDS.128.
__device__ uint4    g_hpk4[B_ * C_ * 256];
__device__ float    g_ssrc[BN];
__device__ float    g_sdst[BN];
__device__ unsigned g_smaxu[B_];
__device__ float2   g_AB[BN];                  // (A, B) per row
__device__ float2   g_EF[BN];                  // (E, F) per col
__device__ uint32_t g_mask[N_ * N_ / 32];      // adj>0.5 bitmask

__device__ __forceinline__ uint32_t smem_u32(const void* p) {
    uint32_t a;
    asm("{ .reg .u64 t; cvta.to.shared.u64 t, %1; cvt.u32.u64 %0, t; }" : "=r"(a) : "l"(p));
    return a;
}
__device__ __forceinline__ void cp_async16(uint32_t dst, const void* src) {
    asm volatile("cp.async.cg.shared.global [%0], [%1], 16;" :: "r"(dst), "l"(src));
}
#define CP_COMMIT() asm volatile("cp.async.commit_group;" ::: "memory")
#define CP_WAIT2()  asm volatile("cp.async.wait_group 2;" ::: "memory")

__device__ __forceinline__ void mma_f16(float* d,
                                        uint32_t a0, uint32_t a1, uint32_t a2, uint32_t a3,
                                        uint32_t b0, uint32_t b1) {
    asm volatile(
        "mma.sync.aligned.m16n8k16.row.col.f32.f16.f16.f32 "
        "{%0,%1,%2,%3},{%4,%5,%6,%7},{%8,%9},{%0,%1,%2,%3};"
        : "+f"(d[0]), "+f"(d[1]), "+f"(d[2]), "+f"(d[3])
        : "r"(a0), "r"(a1), "r"(a2), "r"(a3), "r"(b0), "r"(b1));
}
// tf32 m16n8k8 (validated in R3 on this target)
__device__ __forceinline__ void mma_tf32(float* d,
                                         uint32_t a0, uint32_t a1, uint32_t a2, uint32_t a3,
                                         uint32_t b0, uint32_t b1) {
    asm volatile(
        "mma.sync.aligned.m16n8k8.row.col.f32.tf32.tf32.f32 "
        "{%0,%1,%2,%3},{%4,%5,%6,%7},{%8,%9},{%0,%1,%2,%3};"
        : "+f"(d[0]), "+f"(d[1]), "+f"(d[2]), "+f"(d[3])
        : "r"(a0), "r"(a1), "r"(a2), "r"(a3), "r"(b0), "r"(b1));
}
__device__ __forceinline__ uint32_t h2u(__half2 h) { return *(uint32_t*)&h; }

__device__ __forceinline__ float2 mul2f(ULL ab, ULL ef) {
    ULL q;
    asm("mul.rn.f32x2 %0, %1, %2;" : "=l"(q) : "l"(ab), "l"(ef));
    float2 r;
    asm("mov.b64 {%0,%1}, %2;" : "=f"(r.x), "=f"(r.y) : "l"(q));
    return r;
}
__device__ __forceinline__ ULL pack2f(float x, float y) {
    ULL v; asm("mov.b64 %0, {%1,%2};" : "=l"(v) : "f"(x), "f"(y)); return v;
}
__device__ __forceinline__ ULL ld_s64(uint32_t addr) {
    ULL v; asm volatile("ld.shared.b64 %0, [%1];" : "=l"(v) : "r"(addr)); return v;
}
// keep top 10 mantissa bits (valid for both fp16-hi and tf32-hi splits)
__device__ __forceinline__ float trunc16(float v) {
    return __uint_as_float(__float_as_uint(v) & 0xFFFFE000u);
}
__device__ __forceinline__ unsigned enc_f(float f) {
    unsigned u = __float_as_uint(f);
    return (u & 0x80000000u) ? ~u : (u | 0x80000000u);
}
__device__ __forceinline__ float dec_f(unsigned u) {
    return (u & 0x80000000u) ? __uint_as_float(u ^ 0x80000000u) : __uint_as_float(~u);
}

// ---------------------------------------------------------------------------
// Kernel A: h = input @ W via 3xTF32 mma.sync, fused with adj bitmask, dots,
// batch max, and the packed-fp16 hpk epilogue (permuted, coalesced).
// 128 rows/block, 256 blocks.
// ---------------------------------------------------------------------------
#define ISTR 68                       // float stride of input / h-stage tile
#define WSTR 66                       // uint4 stride of Wpk tile
#define PSTRP 66                      // uint2 stride of pair tile (even!)
#define GS_WPK 0                      // uint4[32*66]  = 33792 B
#define GS_IN  33792                  // float[128*68] = 34816 B
#define GS_AV  (33792 + 34816)        // float[128]
#define GS_TOTAL (GS_AV + 512)

__global__ void __launch_bounds__(256) gemm_h_kernel(const float* __restrict__ in,
                                                     const float* __restrict__ W,
                                                     const float* __restrict__ av,
                                                     const float* __restrict__ adj) {
    extern __shared__ char gs[];
    uint4* wpk = (uint4*)(gs + GS_WPK);
    float* tin = (float*)(gs + GS_IN);
    float* avs = (float*)(gs + GS_AV);
    uint2* ptile = (uint2*)(gs + GS_WPK);   // reuses Wpk region post-k-loop
    __shared__ float red[8];

    const int t = threadIdx.x;
    const int lane = t & 31;
    const int wid = t >> 5;
    const int r0 = lane >> 2;
    const int c0 = lane & 3;
    const int row0 = blockIdx.x * 128;
    const int b = blockIdx.x >> 3;
    const int n0 = row0 & 1023;

    // adj gate loads early (2 jobs of 256 floats per warp)
    const int gw2 = (blockIdx.x * 8 + wid) * 2;
    float mv[16];
#pragma unroll
    for (int j = 0; j < 2; j++)
#pragma unroll
        for (int q = 0; q < 8; q++)
            mv[j * 8 + q] = __ldg(adj + (size_t)(gw2 + j) * 256 + q * 32 + lane);

    // stage input tile 128x64 -> stride-68 smem
#pragma unroll
    for (int i = 0; i < 8; i++) {
        const int e = t + 256 * i;
        const int r = e >> 4;
        const int c4 = (e & 15) * 4;
        const float4 v = __ldg((const float4*)(in + (size_t)(row0 + r) * 64 + c4));
        *(float4*)&tin[r * ISTR + c4] = v;
    }
    // stage W as packed tf32 (hi,lo,hi_k+4,lo_k+4) uint4 tiles
#pragma unroll
    for (int i = 0; i < 8; i++) {
        const int e = t + 256 * i;
        const int kq = e >> 6;              // 0..31
        const int n = e & 63;
        const int k = (kq >> 2) * 8 + (kq & 3);
        const float w0 = __ldg(W + k * 64 + n);
        const float w1 = __ldg(W + (k + 4) * 64 + n);
        const float h0 = trunc16(w0), h1 = trunc16(w1);
        wpk[kq * WSTR + n] = make_uint4(__float_as_uint(h0), __float_as_uint(w0 - h0),
                                        __float_as_uint(h1), __float_as_uint(w1 - h1));
    }
    if (t < 128) avs[t] = __ldg(av + t);
    __syncthreads();

    // ballots -> mask words
#pragma unroll
    for (int j = 0; j < 16; j++) {
        const uint32_t m = __ballot_sync(0xffffffffu, mv[j] > 0.5f);
        if (lane == 0) g_mask[(gw2 + (j >> 3)) * 8 + (j & 7)] = m;
    }

    // 3xTF32 MMA k-loop: warp owns rows row0 + wid*16 .. +15
    float D[8][4];
#pragma unroll
    for (int nb = 0; nb < 8; nb++)
#pragma unroll
        for (int q = 0; q < 4; q++) D[nb][q] = 0.f;

    const float* arow = tin + (wid * 16 + r0) * ISTR;
#pragma unroll
    for (int kk = 0; kk < 8; kk++) {
        const int kb = kk * 8 + c0;
        const float i0 = arow[kb];
        const float i1 = arow[8 * ISTR + kb];
        const float i2 = arow[kb + 4];
        const float i3 = arow[8 * ISTR + kb + 4];
        const float h0 = trunc16(i0), h1 = trunc16(i1), h2 = trunc16(i2), h3 = trunc16(i3);
        const uint32_t ah0 = __float_as_uint(h0), ah1 = __float_as_uint(h1);
        const uint32_t ah2 = __float_as_uint(h2), ah3 = __float_as_uint(h3);
        const uint32_t al0 = __float_as_uint(i0 - h0), al1 = __float_as_uint(i1 - h1);
        const uint32_t al2 = __float_as_uint(i2 - h2), al3 = __float_as_uint(i3 - h3);

        const uint4* wrow = wpk + (kk * 4 + c0) * WSTR + r0;
#pragma unroll
        for (int nb = 0; nb < 8; nb++) {
            const uint4 bv = wrow[nb * 8];
            mma_tf32(D[nb], ah0, ah1, ah2, ah3, bv.x, bv.z);  // ah * wh
            mma_tf32(D[nb], ah0, ah1, ah2, ah3, bv.y, bv.w);  // ah * wl
            mma_tf32(D[nb], al0, al1, al2, al3, bv.x, bv.z);  // al * wh
        }
    }

    // dots from D fragments (rows wid*16+r0 and +8; cols nb*8+2c0, +1)
    float ssA = 0.f, ssB = 0.f, sdA = 0.f, sdB = 0.f;
#pragma unroll
    for (int nb = 0; nb < 8; nb++) {
        const int c = nb * 8 + 2 * c0;
        ssA += D[nb][0] * avs[c] + D[nb][1] * avs[c + 1];
        ssB += D[nb][2] * avs[c] + D[nb][3] * avs[c + 1];
        sdA += D[nb][0] * avs[64 + c] + D[nb][1] * avs[64 + c + 1];
        sdB += D[nb][2] * avs[64 + c] + D[nb][3] * avs[64 + c + 1];
    }
#pragma unroll
    for (int o = 1; o <= 2; o <<= 1) {
        ssA += __shfl_xor_sync(0xffffffffu, ssA, o);
        ssB += __shfl_xor_sync(0xffffffffu, ssB, o);
        sdA += __shfl_xor_sync(0xffffffffu, sdA, o);
        sdB += __shfl_xor_sync(0xffffffffu, sdB, o);
    }
    if (c0 == 0) {
        const int rw = row0 + wid * 16 + r0;
        g_ssrc[rw] = ssA;
        g_ssrc[rw + 8] = ssB;
        g_sdst[rw] = sdA;
        g_sdst[rw + 8] = sdB;
    }
    float sdm = fmaxf(sdA, sdB);
#pragma unroll
    for (int o = 4; o <= 16; o <<= 1) sdm = fmaxf(sdm, __shfl_xor_sync(0xffffffffu, sdm, o));
    if (lane == 0) red[wid] = sdm;

    __syncthreads();   // k-loop smem reads done everywhere; red[] populated
    if (t == 0) {
        float m = red[0];
#pragma unroll
        for (int i = 1; i < 8; i++) m = fmaxf(m, red[i]);
        atomicMax(&g_smaxu[b], enc_f(m));
    }

    // stage h (fp32) into the input region
#pragma unroll
    for (int nb = 0; nb < 8; nb++) {
        const int col = nb * 8 + 2 * c0;
        *(float2*)&tin[(wid * 16 + r0) * ISTR + col] = make_float2(D[nb][0], D[nb][1]);
        *(float2*)&tin[(wid * 16 + r0 + 8) * ISTR + col] = make_float2(D[nb][2], D[nb][3]);
    }
    __syncthreads();

    // pair-build into permuted pair tile (overwrites dead Wpk region)
    {
        const int q = t & 63;          // block-local n-pair 0..63
        const int cg = t >> 6;         // col group 0..3 -> cols cg*16..+15
        const int ti = q >> 5, q32 = q & 31;
        const int pr = ti * 32 + ((q32 >> 3) * 4 + (q32 & 3)) * 2 + ((q32 >> 2) & 1);
        const float* rA = tin + (2 * q) * ISTR + cg * 16;
        const float* rB = rA + ISTR;
#pragma unroll
        for (int j = 0; j < 4; j++) {
            const float4 va = *(const float4*)&rA[4 * j];
            const float4 vb = *(const float4*)&rB[4 * j];
            const float a_[4] = {va.x, va.y, va.z, va.w};
            const float b_[4] = {vb.x, vb.y, vb.z, vb.w};
#pragma unroll
            for (int cc = 0; cc < 4; cc++) {
                const __half ha = __float2half_rn(a_[cc]);
                const __half hb = __float2half_rn(b_[cc]);
                uint2 pk;
                pk.x = h2u(__halves2half2(ha, hb));
                pk.y = h2u(__floats2half2_rn(a_[cc] - __half2float(ha),
                                             b_[cc] - __half2float(hb)));
                ptile[(cg * 16 + 4 * j + cc) * PSTRP + pr] = pk;
            }
        }
    }
    __syncthreads();

    // coalesced copy out (uint4 = 2 consecutive permuted slots)
    const uint4* pt4 = (const uint4*)ptile;
#pragma unroll
    for (int i = 0; i < 8; i++) {
        const int e = t + 256 * i;       // 0..2047
        const int c = e >> 5;
        const int m = e & 31;
        g_hpk4[((size_t)b * 64 + c) * 256 + n0 / 4 + m] = pt4[c * 33 + m];
    }
}

// ---------------------------------------------------------------------------
// Kernel C: factored-softmax coefficients (elementwise)
// ---------------------------------------------------------------------------
__global__ void __launch_bounds__(256) prep_kernel() {
    const int idx = blockIdx.x * 256 + threadIdx.x;
    const int b = idx >> 10;
    const float S = dec_f(g_smaxu[b]);
    const float ss = g_ssrc[idx];
    const float sd = g_sdst[idx];
    float mm = ss + S; mm = mm >= 0.f ? mm : 0.2f * mm;
    g_AB[idx] = make_float2(__expf(ss - mm), __expf(0.2f * ss - mm));
    g_EF[idx] = make_float2(__expf(sd), __expf(0.2f * sd));
}

// ---------------------------------------------------------------------------
// Kernel D: fused attention (unchanged from R13 except g_hpk4 indexing).
// ---------------------------------------------------------------------------
#define PKS4 20                              // uint4 stride per c-row
#define PKBUF4 (64 * PKS4)                   // uint4 per buffer (1280)
#define SMEM_DYN (4 * PKBUF4 * 16 + 4 * 64 * 8)
#define ONES2 0x3C003C00u

__global__ void __launch_bounds__(256, 2) attn_kernel(float* __restrict__ out) {
    extern __shared__ char sm[];
    uint4* pkbase = (uint4*)sm;
    float2* efbase = (float2*)(sm + 4 * PKBUF4 * 16);
    const uint32_t ef_addr0 = smem_u32(efbase);

    const int b = blockIdx.y;
    const int i0 = blockIdx.x * 128;
    const int t = threadIdx.x;
    const int w = t >> 5;
    const int lane = t & 31;
    const int r0 = lane >> 2;
    const int c0 = lane & 3;

    const int irow0 = i0 + w * 16 + r0;
    const int irow1 = irow0 + 8;

    const float2 ab0 = g_AB[b * N_ + irow0];
    const float2 ab1 = g_AB[b * N_ + irow1];
    const ULL AB0 = pack2f(ab0.x, ab0.y);
    const ULL AB1 = pack2f(ab1.x, ab1.y);

    float D[8][4];
#pragma unroll
    for (int nb = 0; nb < 8; nb++)
#pragma unroll
        for (int q = 0; q < 4; q++) D[nb][q] = 0.f;
    float Dl[4] = {0.f, 0.f, 0.f, 0.f};

    const uint32_t* mk0 = g_mask + (size_t)irow0 * 32;
    const uint32_t* mk1 = g_mask + (size_t)irow1 * 32;

    auto stage = [&](int jt) {
        const int buf = jt & 3;
        uint4* pkd = pkbase + buf * PKBUF4;
#pragma unroll
        for (int q = 0; q < 4; q++) {
            const int cid = q * 256 + t;
            const int c = cid >> 4;
            const int part = cid & 15;
            cp_async16(smem_u32(&pkd[c * PKS4 + part]),
                       &g_hpk4[((size_t)b * 64 + c) * 256 + jt * 16 + part]);
        }
        if (t < 32)
            cp_async16(smem_u32(&efbase[buf * 64 + t * 2]), &g_EF[b * N_ + jt * 64 + t * 2]);
    };

    stage(0); CP_COMMIT();
    stage(1); CP_COMMIT();
    stage(2); CP_COMMIT();

    uint32_t mw00 = __ldg(mk0 + 0), mw01 = __ldg(mk0 + 1);
    uint32_t mw10 = __ldg(mk1 + 0), mw11 = __ldg(mk1 + 1);

    for (int jt = 0; jt < 16; jt++) {
        CP_WAIT2();
        __syncthreads();

        if (jt + 3 < 16) stage(jt + 3);
        CP_COMMIT();

        const int jw = (jt < 15) ? (jt + 1) * 2 : 0;
        const uint32_t nw00 = __ldg(mk0 + jw), nw01 = __ldg(mk0 + jw + 1);
        const uint32_t nw10 = __ldg(mk1 + jw), nw11 = __ldg(mk1 + jw + 1);

        const int buf = jt & 3;
        const uint4* pkp = pkbase + buf * PKBUF4;
        const uint32_t efs = ef_addr0 + buf * 512 + 2 * c0 * 8;

        const uint32_t wsh00 = mw00 >> (2 * c0), wsh01 = mw01 >> (2 * c0);
        const uint32_t wsh10 = mw10 >> (2 * c0), wsh11 = mw11 >> (2 * c0);

#pragma unroll
        for (int ks = 0; ks < 4; ks++) {
            const uint32_t ea_addr = efs + ks * 16 * 8;
            const ULL ea = ld_s64(ea_addr);
            const ULL eb = ld_s64(ea_addr + 8);
            const ULL ec = ld_s64(ea_addr + 64);
            const ULL ed = ld_s64(ea_addr + 72);
            const uint32_t ws0 = (ks < 2) ? wsh00 : wsh01;
            const uint32_t ws1 = (ks < 2) ? wsh10 : wsh11;
            const int bo = (ks & 1) << 4;

            float2 q;
            q = mul2f(AB0, ea); float p00 = fmaxf(q.x, q.y);
            q = mul2f(AB0, eb); float p01 = fmaxf(q.x, q.y);
            q = mul2f(AB0, ec); float p02 = fmaxf(q.x, q.y);
            q = mul2f(AB0, ed); float p03 = fmaxf(q.x, q.y);
            q = mul2f(AB1, ea); float p10 = fmaxf(q.x, q.y);
            q = mul2f(AB1, eb); float p11 = fmaxf(q.x, q.y);
            q = mul2f(AB1, ec); float p12 = fmaxf(q.x, q.y);
            q = mul2f(AB1, ed); float p13 = fmaxf(q.x, q.y);

            p00 = ((ws0 >> (bo + 0)) & 1u) ? p00 : 0.f;
            p01 = ((ws0 >> (bo + 1)) & 1u) ? p01 : 0.f;
            p02 = ((ws0 >> (bo + 8)) & 1u) ? p02 : 0.f;
            p03 = ((ws0 >> (bo + 9)) & 1u) ? p03 : 0.f;
            p10 = ((ws1 >> (bo + 0)) & 1u) ? p10 : 0.f;
            p11 = ((ws1 >> (bo + 1)) & 1u) ? p11 : 0.f;
            p12 = ((ws1 >> (bo + 8)) & 1u) ? p12 : 0.f;
            p13 = ((ws1 >> (bo + 9)) & 1u) ? p13 : 0.f;

            const float t00 = trunc16(p00), t01 = trunc16(p01);
            const float t02 = trunc16(p02), t03 = trunc16(p03);
            const float t10 = trunc16(p10), t11 = trunc16(p11);
            const float t12 = trunc16(p12), t13 = trunc16(p13);

            const uint32_t uh0 = h2u(__floats2half2_rn(t00, t01));
            const uint32_t uh1 = h2u(__floats2half2_rn(t10, t11));
            const uint32_t uh2 = h2u(__floats2half2_rn(t02, t03));
            const uint32_t uh3 = h2u(__floats2half2_rn(t12, t13));
            const uint32_t ul0 = h2u(__floats2half2_rn(p00 - t00, p01 - t01));
            const uint32_t ul1 = h2u(__floats2half2_rn(p10 - t10, p11 - t11));
            const uint32_t ul2 = h2u(__floats2half2_rn(p02 - t02, p03 - t03));
            const uint32_t ul3 = h2u(__floats2half2_rn(p12 - t12, p13 - t13));

            // l = Σ(ph + pl) — both terms (R12 showed ph-only is too lossy)
            mma_f16(Dl, uh0, uh1, uh2, uh3, ONES2, ONES2);
            mma_f16(Dl, ul0, ul1, ul2, ul3, ONES2, ONES2);

#pragma unroll
            for (int nb = 0; nb < 8; nb++) {
                const uint4 bv = pkp[(nb * 8 + r0) * PKS4 + ks * 4 + c0];
                mma_f16(D[nb], uh0, uh1, uh2, uh3, bv.x, bv.z);  // ph * hh
                mma_f16(D[nb], uh0, uh1, uh2, uh3, bv.y, bv.w);  // ph * hl
                mma_f16(D[nb], ul0, ul1, ul2, ul3, bv.x, bv.z);  // pl * hh
            }
        }

        mw00 = nw00; mw01 = nw01; mw10 = nw10; mw11 = nw11;
    }

    const float inv0 = 1.0f / Dl[0];
    const float inv1 = 1.0f / Dl[2];

    float2* o0 = (float2*)(out + ((size_t)b * N_ + irow0) * C_ + 2 * c0);
    float2* o1 = (float2*)(out + ((size_t)b * N_ + irow1) * C_ + 2 * c0);
#pragma unroll
    for (int nb = 0; nb < 8; nb++) {
        float v0 = D[nb][0] * inv0;
        float v1 = D[nb][1] * inv0;
        float v2 = D[nb][2] * inv1;
        float v3 = D[nb][3] * inv1;
        v0 = v0 > 0.f ? v0 : (__expf(v0) - 1.0f);
        v1 = v1 > 0.f ? v1 : (__expf(v1) - 1.0f);
        v2 = v2 > 0.f ? v2 : (__expf(v2) - 1.0f);
        v3 = v3 > 0.f ? v3 : (__expf(v3) - 1.0f);
        o0[nb * 4] = make_float2(v0, v1);
        o1[nb * 4] = make_float2(v2, v3);
    }
}

// ---------------------------------------------------------------------------
extern "C" void kernel_launch(void* const* d_in, const int* in_sizes, int n_in,
                              void* d_out, int out_size) {
    const float* input = (const float*)d_in[0];  // (32,1024,64)
    const float* adj   = (const float*)d_in[1];  // (1024,1024)
    const float* W     = (const float*)d_in[2];  // (64,64)
    const float* a     = (const float*)d_in[3];  // (128,1)
    float* out = (float*)d_out;

    cudaFuncSetAttribute(gemm_h_kernel, cudaFuncAttributeMaxDynamicSharedMemorySize, GS_TOTAL);
    cudaFuncSetAttribute(attn_kernel, cudaFuncAttributeMaxDynamicSharedMemorySize, SMEM_DYN);

    gemm_h_kernel<<<BN / 128, 256, GS_TOTAL>>>(input, W, a, adj);
    prep_kernel<<<BN / 256, 256>>>();
    attn_kernel<<<dim3(N_ / 128, B_), 256, SMEM_DYN>>>(out);
}